// round 4
// baseline (speedup 1.0000x reference)
#include <cuda_runtime.h>
#include <math.h>

// ---------------- problem constants ----------------
#define BATCH  128
#define LSEQ   16
#define EMB    768
#define DHALF  384
#define HEADS  12
#define HDIM   64
#define NL     6
#define SEQ    12
#define NLIDX  15
#define FF     3072
#define TOK    (NLIDX * BATCH * SEQ)        // 23040
#define TE     (TOK * EMB)                  // 17694720
#define TFF    (TOK * FF)

// ---------------- scratch (device globals; no cudaMalloc allowed) ----------------
__device__ float g_x[TE];
__device__ float g_h[TE];
__device__ float g_q[TE];
__device__ float g_k[TE];
__device__ float g_v[TE];
__device__ float g_o[TE];
__device__ float g_mlp[TFF];
__device__ float g_logits[NLIDX * BATCH * 3];
__device__ float g_losses[NLIDX];

// ---------------- input assembly ----------------
// token t = lidx*1536 + b*12 + s ; feature e
// s<3   : cos features of X[:, 15-lidx] (e<384) and X[:, 14-lidx] (e>=384), coord c=s
// 3<=s<6: targets[src_b, (16-lidx)%16, s-3] broadcast over e
// s>=6  : constant (15 - lidx)
__global__ __launch_bounds__(256) void assemble_kernel(
    const float* __restrict__ X, const float* __restrict__ targets,
    const float* __restrict__ omegas, const float* __restrict__ phases,
    const int* __restrict__ perms, float* __restrict__ xout)
{
    int idx = blockIdx.x * blockDim.x + threadIdx.x;
    if (idx >= TE) return;
    int e = idx % EMB;
    int t = idx / EMB;
    int s = t % SEQ;
    int b = (t / SEQ) % BATCH;
    int lidx = t / (SEQ * BATCH);           // 0..14  (ref lidx = this+1)
    int sb = perms[lidx * BATCH + b];

    float val;
    if (s < 3) {
        int c = s;
        int ti = (e < DHALF) ? (15 - lidx) : (14 - lidx);
        int d  = (e < DHALF) ? e : (e - DHALF);
        float xv = X[(sb * LSEQ + ti) * 3 + c];
        val = cosf(xv * omegas[c * DHALF + d] + phases[c * DHALF + d]);
    } else if (s < 6) {
        int c = s - 3;
        int ti = (16 - lidx) % 16;
        val = targets[(sb * LSEQ + ti) * 3 + c];
    } else {
        val = (float)(15 - lidx);
    }
    xout[idx] = val;
}

// ---------------- layernorm: one block per token ----------------
__global__ __launch_bounds__(256) void ln_kernel(
    const float* __restrict__ in, float* __restrict__ out,
    const float* __restrict__ gam, const float* __restrict__ bet)
{
    __shared__ float red[256];
    __shared__ float s_mu, s_rs;
    int t = blockIdx.x;
    int tid = threadIdx.x;
    const float* x = in + (size_t)t * EMB;

    float v0 = x[tid], v1 = x[tid + 256], v2 = x[tid + 512];
    red[tid] = v0 + v1 + v2;
    __syncthreads();
    for (int s = 128; s > 0; s >>= 1) {
        if (tid < s) red[tid] += red[tid + s];
        __syncthreads();
    }
    if (tid == 0) s_mu = red[0] * (1.0f / EMB);
    __syncthreads();
    float mu = s_mu;
    float d0 = v0 - mu, d1 = v1 - mu, d2 = v2 - mu;
    red[tid] = d0 * d0 + d1 * d1 + d2 * d2;
    __syncthreads();
    for (int s = 128; s > 0; s >>= 1) {
        if (tid < s) red[tid] += red[tid + s];
        __syncthreads();
    }
    if (tid == 0) s_rs = rsqrtf(red[0] * (1.0f / EMB) + 1e-3f);
    __syncthreads();
    float rs = s_rs;
    float* o = out + (size_t)t * EMB;
    o[tid]       = d0 * rs * gam[tid]       + bet[tid];
    o[tid + 256] = d1 * rs * gam[tid + 256] + bet[tid + 256];
    o[tid + 512] = d2 * rs * gam[tid + 512] + bet[tid + 512];
}

// ---------------- SGEMM: C[M,N] = A[M,K] @ B[K,N] (+bias, epilogue variants) ----------------
// EPI 0: C = acc + bias      (QKV)
// EPI 1: C = C + acc + bias  (residual accumulate)
// EPI 2: C = relu(acc+bias)  (MLP up)
// BM=BN=128, BK=8, 256 threads, 8x8 per thread. M,N multiples of 128; K multiple of 8.
template <int EPI>
__global__ __launch_bounds__(256, 2) void sgemm128(
    const float* __restrict__ A, const float* __restrict__ B,
    const float* __restrict__ bias, float* __restrict__ C,
    int M, int N, int K)
{
    __shared__ float As[8][128];
    __shared__ float Bs[8][128];

    const int t  = threadIdx.x;
    const int tx = t & 15;
    const int ty = t >> 4;
    const int row0 = blockIdx.y * 128;
    const int col0 = blockIdx.x * 128;

    const int arow  = t >> 1;
    const int akoff = (t & 1) * 4;
    const int bkk   = t >> 5;
    const int bcol  = (t & 31) * 4;

    float acc[8][8];
#pragma unroll
    for (int i = 0; i < 8; ++i)
#pragma unroll
        for (int j = 0; j < 8; ++j) acc[i][j] = 0.0f;

    const float* Aptr = A + (size_t)(row0 + arow) * K + akoff;
    const float* Bptr = B + (size_t)bkk * N + col0 + bcol;

    float4 a4 = *(const float4*)Aptr;
    float4 b4 = *(const float4*)Bptr;

    const int nch = K >> 3;
    for (int ch = 0; ch < nch; ++ch) {
        __syncthreads();
        As[akoff + 0][arow] = a4.x;
        As[akoff + 1][arow] = a4.y;
        As[akoff + 2][arow] = a4.z;
        As[akoff + 3][arow] = a4.w;
        *(float4*)&Bs[bkk][bcol] = b4;
        __syncthreads();
        if (ch + 1 < nch) {
            a4 = *(const float4*)(Aptr + (size_t)(ch + 1) * 8);
            b4 = *(const float4*)(Bptr + (size_t)(ch + 1) * 8 * N);
        }
#pragma unroll
        for (int kk = 0; kk < 8; ++kk) {
            float ra[8], rb[8];
            *(float4*)&ra[0] = *(const float4*)&As[kk][ty * 8];
            *(float4*)&ra[4] = *(const float4*)&As[kk][ty * 8 + 4];
            *(float4*)&rb[0] = *(const float4*)&Bs[kk][tx * 8];
            *(float4*)&rb[4] = *(const float4*)&Bs[kk][tx * 8 + 4];
#pragma unroll
            for (int i = 0; i < 8; ++i)
#pragma unroll
                for (int j = 0; j < 8; ++j)
                    acc[i][j] += ra[i] * rb[j];
        }
    }

#pragma unroll
    for (int i = 0; i < 8; ++i) {
        int r = row0 + ty * 8 + i;
        float* Crow = C + (size_t)r * N + col0 + tx * 8;
        const float* brow = bias + col0 + tx * 8;
#pragma unroll
        for (int j = 0; j < 8; ++j) {
            float vv = acc[i][j] + brow[j];
            if (EPI == 1) vv += Crow[j];
            if (EPI == 2) vv = fmaxf(vv, 0.0f);
            Crow[j] = vv;
        }
    }
}

// ---------------- attention: one block per (instance, head). seq=12, hd=64 ----------------
__global__ __launch_bounds__(192) void attn_kernel(
    const float* __restrict__ q, const float* __restrict__ k,
    const float* __restrict__ v, float* __restrict__ o)
{
    int inst = blockIdx.x;       // 0..1919  (lidx*128 + b)
    int h    = blockIdx.y;       // 0..11
    int base = inst * SEQ;
    int tid  = threadIdx.x;

    __shared__ float qs[SEQ][HDIM], ks[SEQ][HDIM], vs[SEQ][HDIM];
    __shared__ float sc[SEQ][SEQ], ps[SEQ][SEQ];

    for (int idx = tid; idx < SEQ * HDIM; idx += 192) {
        int s = idx >> 6, d = idx & 63;
        size_t g = (size_t)(base + s) * EMB + h * HDIM + d;
        qs[s][d] = q[g];
        ks[s][d] = k[g];
        vs[s][d] = v[g];
    }
    __syncthreads();

    if (tid < SEQ * SEQ) {
        int i = tid / SEQ, j = tid % SEQ;
        float a = 0.0f;
#pragma unroll
        for (int d = 0; d < HDIM; ++d) a += qs[i][d] * ks[j][d];
        sc[i][j] = a * 0.125f;
    }
    __syncthreads();

    if (tid < SEQ) {
        float mx = -1e30f;
#pragma unroll
        for (int j = 0; j < SEQ; ++j) mx = fmaxf(mx, sc[tid][j]);
        float sum = 0.0f;
#pragma unroll
        for (int j = 0; j < SEQ; ++j) { float ev = expf(sc[tid][j] - mx); ps[tid][j] = ev; sum += ev; }
        float inv = 1.0f / sum;
#pragma unroll
        for (int j = 0; j < SEQ; ++j) ps[tid][j] *= inv;
    }
    __syncthreads();

    for (int idx = tid; idx < SEQ * HDIM; idx += 192) {
        int i = idx >> 6, d = idx & 63;
        float a = 0.0f;
#pragma unroll
        for (int j = 0; j < SEQ; ++j) a += ps[i][j] * vs[j][d];
        o[(size_t)(base + i) * EMB + h * HDIM + d] = a;
    }
}

// ---------------- output projection: logits[inst,0..2] = row(9216) @ Wout + bout ----------------
__global__ __launch_bounds__(256) void outproj_kernel(
    const float* __restrict__ h, const float* __restrict__ Wout,
    const float* __restrict__ bout, float* __restrict__ logits)
{
    __shared__ float r0[256], r1[256], r2[256];
    int inst = blockIdx.x;                 // 0..1919
    int tid = threadIdx.x;
    const float* row = h + (size_t)inst * (SEQ * EMB);
    float a0 = 0, a1 = 0, a2 = 0;
    for (int kk = tid; kk < SEQ * EMB; kk += 256) {
        float x = row[kk];
        const float* w = Wout + kk * 3;
        a0 += x * w[0]; a1 += x * w[1]; a2 += x * w[2];
    }
    r0[tid] = a0; r1[tid] = a1; r2[tid] = a2;
    __syncthreads();
    for (int s = 128; s > 0; s >>= 1) {
        if (tid < s) { r0[tid] += r0[tid + s]; r1[tid] += r1[tid + s]; r2[tid] += r2[tid + s]; }
        __syncthreads();
    }
    if (tid == 0) {
        logits[inst * 3 + 0] = r0[0] + bout[0];
        logits[inst * 3 + 1] = r1[0] + bout[1];
        logits[inst * 3 + 2] = r2[0] + bout[2];
    }
}

// ---------------- greedy matching + loss: one block per lidx ----------------
// Equivalent to stable-argsort greedy scan: 128 rounds of argmin over keys
// (cost_bits<<32 | flat_idx); assigned rows/cols get their keys set to MAX.
__global__ __launch_bounds__(1024) void match_kernel(
    const float* __restrict__ logits, const float* __restrict__ targets,
    float* __restrict__ losses)
{
    extern __shared__ unsigned long long keys[];     // 16384 u64 = 128 KB
    __shared__ int rowm[BATCH];
    __shared__ unsigned long long warpmin[32];
    __shared__ float red[1024];

    int lidx = blockIdx.x;                 // 0..14
    int tid = threadIdx.x;
    int tref = 15 - lidx;                  // target time index for this lidx
    const float* lg = logits + lidx * BATCH * 3;

    for (int e = tid; e < BATCH * BATCH; e += 1024) {
        int i = e >> 7, j = e & 127;
        float dx = lg[i * 3 + 0] - targets[(j * LSEQ + tref) * 3 + 0];
        float dy = lg[i * 3 + 1] - targets[(j * LSEQ + tref) * 3 + 1];
        float dz = lg[i * 3 + 2] - targets[(j * LSEQ + tref) * 3 + 2];
        float c = sqrtf(dx * dx + dy * dy + dz * dz + 1e-12f);
        keys[e] = ((unsigned long long)__float_as_uint(c) << 32) | (unsigned int)e;
    }
    __syncthreads();

    for (int r = 0; r < BATCH; ++r) {
        unsigned long long m = ~0ull;
        for (int e = tid; e < BATCH * BATCH; e += 1024) {
            unsigned long long kk = keys[e];
            m = (kk < m) ? kk : m;
        }
#pragma unroll
        for (int o = 16; o > 0; o >>= 1) {
            unsigned long long other = __shfl_down_sync(0xffffffffu, m, o);
            m = (other < m) ? other : m;
        }
        if ((tid & 31) == 0) warpmin[tid >> 5] = m;
        __syncthreads();
        if (tid < 32) {
            unsigned long long mm = warpmin[tid];
#pragma unroll
            for (int o = 16; o > 0; o >>= 1) {
                unsigned long long other = __shfl_down_sync(0xffffffffu, mm, o);
                mm = (other < mm) ? other : mm;
            }
            if (tid == 0) warpmin[0] = mm;
        }
        __syncthreads();
        unsigned long long best = warpmin[0];
        int e = (int)(best & 0xffffffffull);
        int bi = e >> 7, bj = e & 127;
        if (tid < BATCH) {
            keys[bi * BATCH + tid] = ~0ull;
            keys[tid * BATCH + bj] = ~0ull;
        }
        if (tid == 0) rowm[bi] = bj;
        __syncthreads();
    }

    float part = 0.0f;
    if (tid < BATCH * 3) {
        int i = tid / 3, c = tid % 3;
        float d = lg[rowm[i] * 3 + c] - targets[(i * LSEQ + tref) * 3 + c];
        part = d * d;
    }
    red[tid] = part;
    __syncthreads();
    for (int s = 512; s > 0; s >>= 1) {
        if (tid < s) red[tid] += red[tid + s];
        __syncthreads();
    }
    if (tid == 0) losses[lidx] = red[0] * (1.0f / (BATCH * 3));
}

__global__ void final_mean_kernel(const float* __restrict__ losses, float* __restrict__ out)
{
    if (threadIdx.x == 0 && blockIdx.x == 0) {
        float s = 0.0f;
        for (int i = 0; i < NLIDX; ++i) s += losses[i];
        out[0] = s * (1.0f / NLIDX);
    }
}

// ---------------- launch ----------------
extern "C" void kernel_launch(void* const* d_in, const int* in_sizes, int n_in,
                              void* d_out, int out_size)
{
    (void)in_sizes; (void)n_in; (void)out_size;
    const float* X    = (const float*)d_in[0];
    const float* tg   = (const float*)d_in[1];
    const float* om   = (const float*)d_in[2];
    const float* ph   = (const float*)d_in[3];
    const int*   pm   = (const int*)  d_in[4];
    const float* Wq   = (const float*)d_in[5];
    const float* bq   = (const float*)d_in[6];
    const float* Wk   = (const float*)d_in[7];
    const float* bk   = (const float*)d_in[8];
    const float* Wv   = (const float*)d_in[9];
    const float* bv   = (const float*)d_in[10];
    const float* Wo   = (const float*)d_in[11];
    const float* bo   = (const float*)d_in[12];
    const float* l1g  = (const float*)d_in[13];
    const float* l1b  = (const float*)d_in[14];
    const float* l2g  = (const float*)d_in[15];
    const float* l2b  = (const float*)d_in[16];
    const float* W1   = (const float*)d_in[17];
    const float* b1   = (const float*)d_in[18];
    const float* W2   = (const float*)d_in[19];
    const float* b2   = (const float*)d_in[20];
    const float* lfg  = (const float*)d_in[21];
    const float* lfb  = (const float*)d_in[22];
    const float* Wout = (const float*)d_in[23];
    const float* bout = (const float*)d_in[24];

    float *px, *phh, *pq, *pk, *pv, *po, *pmlp, *plog, *plos;
    cudaGetSymbolAddress((void**)&px,   g_x);
    cudaGetSymbolAddress((void**)&phh,  g_h);
    cudaGetSymbolAddress((void**)&pq,   g_q);
    cudaGetSymbolAddress((void**)&pk,   g_k);
    cudaGetSymbolAddress((void**)&pv,   g_v);
    cudaGetSymbolAddress((void**)&po,   g_o);
    cudaGetSymbolAddress((void**)&pmlp, g_mlp);
    cudaGetSymbolAddress((void**)&plog, g_logits);
    cudaGetSymbolAddress((void**)&plos, g_losses);

    cudaFuncSetAttribute(match_kernel,
                         cudaFuncAttributeMaxDynamicSharedMemorySize, 131072);

    assemble_kernel<<<(TE + 255) / 256, 256>>>(X, tg, om, ph, pm, px);

    dim3 g768(EMB / 128, TOK / 128);     // (6, 180)
    dim3 g3072(FF / 128, TOK / 128);     // (24, 180)
    for (int l = 0; l < NL; ++l) {
        size_t wE = (size_t)l * EMB * EMB;
        size_t wF = (size_t)l * EMB * FF;
        ln_kernel<<<TOK, 256>>>(px, phh, l1g + l * EMB, l1b + l * EMB);
        sgemm128<0><<<g768, 256>>>(phh, Wq + wE, bq + l * EMB, pq, TOK, EMB, EMB);
        sgemm128<0><<<g768, 256>>>(phh, Wk + wE, bk + l * EMB, pk, TOK, EMB, EMB);
        sgemm128<0><<<g768, 256>>>(phh, Wv + wE, bv + l * EMB, pv, TOK, EMB, EMB);
        attn_kernel<<<dim3(NLIDX * BATCH, HEADS), 192>>>(pq, pk, pv, po);
        sgemm128<1><<<g768, 256>>>(po, Wo + wE, bo + l * EMB, px, TOK, EMB, EMB);
        ln_kernel<<<TOK, 256>>>(px, phh, l2g + l * EMB, l2b + l * EMB);
        sgemm128<2><<<g3072, 256>>>(phh, W1 + wF, b1 + l * FF, pmlp, TOK, FF, EMB);
        sgemm128<1><<<g768, 256>>>(pmlp, W2 + wF, b2 + l * EMB, px, TOK, EMB, FF);
    }
    ln_kernel<<<TOK, 256>>>(px, phh, lfg, lfb);
    outproj_kernel<<<NLIDX * BATCH, 256>>>(phh, Wout, bout, plog);
    match_kernel<<<NLIDX, 1024, 131072>>>(plog, tg, plos);
    final_mean_kernel<<<1, 32>>>(plos, (float*)d_out);
}

// round 7
// speedup vs baseline: 1.6800x; 1.6800x over previous
#include <cuda_runtime.h>
#include <cuda_bf16.h>
#include <math.h>

// ---------------- problem constants ----------------
#define BATCH  128
#define LSEQ   16
#define EMB    768
#define DHALF  384
#define HEADS  12
#define HDIM   64
#define NL     6
#define SEQ    12
#define NLIDX  15
#define FF     3072
#define TOK    (NLIDX * BATCH * SEQ)        // 23040
#define TE     (TOK * EMB)                  // 17694720
#define TFF    (TOK * FF)

#define WQKV   (EMB * EMB)                  // 589824
#define WFFN   (EMB * FF)                   // 2359296
#define WLAYER (4 * WQKV + 2 * WFFN)        // 7077888

// ---------------- scratch (device globals; no cudaMalloc allowed) ----------------
__device__ float g_x[TE];
__device__ float g_h[TE];
__device__ float g_q[TE];
__device__ float g_k[TE];
__device__ float g_v[TE];
__device__ float g_o[TE];
__device__ float g_mlp[TFF];
__device__ float g_logits[NLIDX * BATCH * 3];
__device__ float g_losses[NLIDX];
// pre-transposed, k-tiled, bf16-split weights: layout [kt][n][16] per matrix
__device__ __nv_bfloat16 g_whi[NL * WLAYER];
__device__ __nv_bfloat16 g_wlo[NL * WLAYER];

// ---------------- small helpers ----------------
static __device__ __forceinline__ unsigned int bf2_bits(__nv_bfloat162 v) {
    return *reinterpret_cast<unsigned int*>(&v);
}
static __device__ __forceinline__ unsigned int smem_u32(const void* p) {
    return (unsigned int)__cvta_generic_to_shared(p);
}
static __device__ __forceinline__ void ldsm4(unsigned int* r, unsigned int addr) {
    asm volatile("ldmatrix.sync.aligned.m8n8.x4.shared.b16 {%0,%1,%2,%3}, [%4];"
                 : "=r"(r[0]), "=r"(r[1]), "=r"(r[2]), "=r"(r[3]) : "r"(addr));
}
static __device__ __forceinline__ void mma_bf16(float* c, const unsigned int* a,
                                                unsigned int b0, unsigned int b1) {
    asm volatile(
        "mma.sync.aligned.m16n8k16.row.col.f32.bf16.bf16.f32 "
        "{%0,%1,%2,%3}, {%4,%5,%6,%7}, {%8,%9}, {%0,%1,%2,%3};"
        : "+f"(c[0]), "+f"(c[1]), "+f"(c[2]), "+f"(c[3])
        : "r"(a[0]), "r"(a[1]), "r"(a[2]), "r"(a[3]), "r"(b0), "r"(b1));
}

// ---------------- weight prep: W[K][N] fp32 -> tiled-transposed bf16 hi/lo ----------------
// out layout: element (k, n) -> [( (k/16)*N + n )*16 + k%16]
__global__ __launch_bounds__(256) void wprep_kernel(
    const float* __restrict__ W, __nv_bfloat16* __restrict__ hi,
    __nv_bfloat16* __restrict__ lo, int N)
{
    int n  = blockIdx.x * 256 + threadIdx.x;
    int kt = blockIdx.y;
    float v[16];
#pragma unroll
    for (int k = 0; k < 16; ++k)
        v[k] = W[(size_t)(kt * 16 + k) * N + n];

    unsigned int uh[8], ul[8];
#pragma unroll
    for (int j = 0; j < 8; ++j) {
        float x0 = v[2 * j], x1 = v[2 * j + 1];
        __nv_bfloat16 h0 = __float2bfloat16_rn(x0);
        __nv_bfloat16 h1 = __float2bfloat16_rn(x1);
        float l0 = x0 - __bfloat162float(h0);
        float l1 = x1 - __bfloat162float(h1);
        __nv_bfloat162 hp; hp.x = h0; hp.y = h1;
        uh[j] = bf2_bits(hp);
        __nv_bfloat162 lp = __floats2bfloat162_rn(l0, l1);
        ul[j] = bf2_bits(lp);
    }
    size_t base = ((size_t)kt * N + n) * 16;
    uint4* ph = reinterpret_cast<uint4*>(hi + base);
    ph[0] = make_uint4(uh[0], uh[1], uh[2], uh[3]);
    ph[1] = make_uint4(uh[4], uh[5], uh[6], uh[7]);
    uint4* pl = reinterpret_cast<uint4*>(lo + base);
    pl[0] = make_uint4(ul[0], ul[1], ul[2], ul[3]);
    pl[1] = make_uint4(ul[4], ul[5], ul[6], ul[7]);
}

// ---------------- input assembly ----------------
__global__ __launch_bounds__(256) void assemble_kernel(
    const float* __restrict__ X, const float* __restrict__ targets,
    const float* __restrict__ omegas, const float* __restrict__ phases,
    const int* __restrict__ perms, float* __restrict__ xout)
{
    int idx = blockIdx.x * blockDim.x + threadIdx.x;
    if (idx >= TE) return;
    int e = idx % EMB;
    int t = idx / EMB;
    int s = t % SEQ;
    int b = (t / SEQ) % BATCH;
    int lidx = t / (SEQ * BATCH);
    int sb = perms[lidx * BATCH + b];

    float val;
    if (s < 3) {
        int c = s;
        int ti = (e < DHALF) ? (15 - lidx) : (14 - lidx);
        int d  = (e < DHALF) ? e : (e - DHALF);
        float xv = X[(sb * LSEQ + ti) * 3 + c];
        val = cosf(xv * omegas[c * DHALF + d] + phases[c * DHALF + d]);
    } else if (s < 6) {
        int c = s - 3;
        int ti = (16 - lidx) % 16;
        val = targets[(sb * LSEQ + ti) * 3 + c];
    } else {
        val = (float)(15 - lidx);
    }
    xout[idx] = val;
}

// ---------------- layernorm: one block per token ----------------
__global__ __launch_bounds__(256) void ln_kernel(
    const float* __restrict__ in, float* __restrict__ out,
    const float* __restrict__ gam, const float* __restrict__ bet)
{
    __shared__ float red[256];
    __shared__ float s_mu, s_rs;
    int t = blockIdx.x;
    int tid = threadIdx.x;
    const float* x = in + (size_t)t * EMB;

    float v0 = x[tid], v1 = x[tid + 256], v2 = x[tid + 512];
    red[tid] = v0 + v1 + v2;
    __syncthreads();
    for (int s = 128; s > 0; s >>= 1) {
        if (tid < s) red[tid] += red[tid + s];
        __syncthreads();
    }
    if (tid == 0) s_mu = red[0] * (1.0f / EMB);
    __syncthreads();
    float mu = s_mu;
    float d0 = v0 - mu, d1 = v1 - mu, d2 = v2 - mu;
    red[tid] = d0 * d0 + d1 * d1 + d2 * d2;
    __syncthreads();
    for (int s = 128; s > 0; s >>= 1) {
        if (tid < s) red[tid] += red[tid + s];
        __syncthreads();
    }
    if (tid == 0) s_rs = rsqrtf(red[0] * (1.0f / EMB) + 1e-3f);
    __syncthreads();
    float rs = s_rs;
    float* o = out + (size_t)t * EMB;
    o[tid]       = d0 * rs * gam[tid]       + bet[tid];
    o[tid + 256] = d1 * rs * gam[tid + 256] + bet[tid + 256];
    o[tid + 512] = d2 * rs * gam[tid + 512] + bet[tid + 512];
}

// ---------------- bf16x3 tensor-core GEMM ----------------
// C[M,N] = A[M,K] (fp32, split on the fly) @ Bsplit[K,N] (pre-split bf16 hi/lo,
// tiled-transposed layout). Error ~2^-18 per term (near-fp32).
// EPI 0: C = acc + bias ; 1: C += acc + bias ; 2: C = relu(acc + bias)
// Block 128x128, BK=16, 8 warps as 2(m) x 4(n), warp tile 64x32.
template <int EPI>
__global__ __launch_bounds__(256) void gemm_bf16x3(
    const float* __restrict__ A, const __nv_bfloat16* __restrict__ Bhi,
    const __nv_bfloat16* __restrict__ Blo, const float* __restrict__ bias,
    float* __restrict__ C, int M, int N, int K)
{
    __shared__ __align__(16) __nv_bfloat16 AsH[128][24];
    __shared__ __align__(16) __nv_bfloat16 AsL[128][24];
    __shared__ __align__(16) __nv_bfloat16 BsH[128][24];
    __shared__ __align__(16) __nv_bfloat16 BsL[128][24];

    const int t = threadIdx.x;
    const int lane = t & 31, wid = t >> 5;
    const int wm = wid >> 2, wn = wid & 3;
    const int row0 = blockIdx.y * 128, col0 = blockIdx.x * 128;

    float acc[4][4][4];
#pragma unroll
    for (int i = 0; i < 4; ++i)
#pragma unroll
        for (int j = 0; j < 4; ++j)
#pragma unroll
            for (int k = 0; k < 4; ++k) acc[i][j][k] = 0.0f;

    // global staging
    const int sArow = t >> 2;            // 0..63 (and +64)
    const int sAk   = (t & 3) * 4;
    const int sBrow = t >> 1;            // 0..127
    const int sBoff = (t & 1) * 8;
    const float* Ap0 = A + (size_t)(row0 + sArow) * K + sAk;
    const float* Ap1 = Ap0 + (size_t)64 * K;
    const __nv_bfloat16* BhP = Bhi + (size_t)col0 * 16 + t * 8;
    const __nv_bfloat16* BlP = Blo + (size_t)col0 * 16 + t * 8;

    float4 a0 = *(const float4*)Ap0;
    float4 a1 = *(const float4*)Ap1;
    uint4  bh = *(const uint4*)BhP;
    uint4  bl = *(const uint4*)BlP;

    // ldmatrix source addresses
    const int arow  = wm * 64 + (lane & 15);
    const int abyte = (lane >> 4) << 4;
    const unsigned int aH = smem_u32(&AsH[0][0]) + arow * 48 + abyte;
    const unsigned int aL = smem_u32(&AsL[0][0]) + arow * 48 + abyte;
    const int brow  = wn * 32 + (lane & 7) + ((lane >> 4) << 3);
    const int bbyte = ((lane >> 3) & 1) << 4;
    const unsigned int bH = smem_u32(&BsH[0][0]) + brow * 48 + bbyte;
    const unsigned int bL = smem_u32(&BsL[0][0]) + brow * 48 + bbyte;

    const int nkt = K >> 4;
    for (int kt = 0; kt < nkt; ++kt) {
        __syncthreads();
        // split+store A staging (two rows)
        {
            float4 v = a0;
            __nv_bfloat16 h0 = __float2bfloat16_rn(v.x), h1 = __float2bfloat16_rn(v.y);
            __nv_bfloat16 h2 = __float2bfloat16_rn(v.z), h3 = __float2bfloat16_rn(v.w);
            __nv_bfloat162 pA; pA.x = h0; pA.y = h1;
            __nv_bfloat162 pB; pB.x = h2; pB.y = h3;
            *(uint2*)&AsH[sArow][sAk] = make_uint2(bf2_bits(pA), bf2_bits(pB));
            __nv_bfloat162 lA = __floats2bfloat162_rn(v.x - __bfloat162float(h0),
                                                      v.y - __bfloat162float(h1));
            __nv_bfloat162 lB = __floats2bfloat162_rn(v.z - __bfloat162float(h2),
                                                      v.w - __bfloat162float(h3));
            *(uint2*)&AsL[sArow][sAk] = make_uint2(bf2_bits(lA), bf2_bits(lB));
        }
        {
            float4 v = a1;
            __nv_bfloat16 h0 = __float2bfloat16_rn(v.x), h1 = __float2bfloat16_rn(v.y);
            __nv_bfloat16 h2 = __float2bfloat16_rn(v.z), h3 = __float2bfloat16_rn(v.w);
            __nv_bfloat162 pA; pA.x = h0; pA.y = h1;
            __nv_bfloat162 pB; pB.x = h2; pB.y = h3;
            *(uint2*)&AsH[sArow + 64][sAk] = make_uint2(bf2_bits(pA), bf2_bits(pB));
            __nv_bfloat162 lA = __floats2bfloat162_rn(v.x - __bfloat162float(h0),
                                                      v.y - __bfloat162float(h1));
            __nv_bfloat162 lB = __floats2bfloat162_rn(v.z - __bfloat162float(h2),
                                                      v.w - __bfloat162float(h3));
            *(uint2*)&AsL[sArow + 64][sAk] = make_uint2(bf2_bits(lA), bf2_bits(lB));
        }
        *(uint4*)&BsH[sBrow][sBoff] = bh;
        *(uint4*)&BsL[sBrow][sBoff] = bl;
        __syncthreads();

        if (kt + 1 < nkt) {
            a0 = *(const float4*)(Ap0 + (size_t)(kt + 1) * 16);
            a1 = *(const float4*)(Ap1 + (size_t)(kt + 1) * 16);
            bh = *(const uint4*)(BhP + (size_t)(kt + 1) * N * 16);
            bl = *(const uint4*)(BlP + (size_t)(kt + 1) * N * 16);
        }

        unsigned int Bh[2][4], Bl[2][4];
        ldsm4(Bh[0], bH);
        ldsm4(Bh[1], bH + 16 * 48);
        ldsm4(Bl[0], bL);
        ldsm4(Bl[1], bL + 16 * 48);

#pragma unroll
        for (int mi = 0; mi < 4; ++mi) {
            unsigned int Ah[4], Al[4];
            ldsm4(Ah, aH + mi * 16 * 48);
            ldsm4(Al, aL + mi * 16 * 48);
#pragma unroll
            for (int p = 0; p < 2; ++p)
#pragma unroll
                for (int q = 0; q < 2; ++q) {
                    float* c = acc[mi][p * 2 + q];
                    mma_bf16(c, Ah, Bh[p][2 * q], Bh[p][2 * q + 1]);
                    mma_bf16(c, Ah, Bl[p][2 * q], Bl[p][2 * q + 1]);
                    mma_bf16(c, Al, Bh[p][2 * q], Bh[p][2 * q + 1]);
                }
        }
    }

    // epilogue
    const int rbase = row0 + wm * 64 + (lane >> 2);
    const int cbase = col0 + wn * 32 + (lane & 3) * 2;
#pragma unroll
    for (int ni = 0; ni < 4; ++ni) {
        int cb = cbase + ni * 8;
        float2 bi = *(const float2*)&bias[cb];
#pragma unroll
        for (int mi = 0; mi < 4; ++mi) {
            float* c = acc[mi][ni];
            float* p0 = C + (size_t)(rbase + mi * 16) * N + cb;
            float* p1 = p0 + (size_t)8 * N;
            float2 v0 = make_float2(c[0] + bi.x, c[1] + bi.y);
            float2 v1 = make_float2(c[2] + bi.x, c[3] + bi.y);
            if (EPI == 1) {
                float2 o0 = *(float2*)p0, o1 = *(float2*)p1;
                v0.x += o0.x; v0.y += o0.y;
                v1.x += o1.x; v1.y += o1.y;
            }
            if (EPI == 2) {
                v0.x = fmaxf(v0.x, 0.0f); v0.y = fmaxf(v0.y, 0.0f);
                v1.x = fmaxf(v1.x, 0.0f); v1.y = fmaxf(v1.y, 0.0f);
            }
            *(float2*)p0 = v0;
            *(float2*)p1 = v1;
        }
    }
}

// ---------------- attention: one block per (instance, head). seq=12, hd=64 ----------------
__global__ __launch_bounds__(192) void attn_kernel(
    const float* __restrict__ q, const float* __restrict__ k,
    const float* __restrict__ v, float* __restrict__ o)
{
    int inst = blockIdx.x;
    int h    = blockIdx.y;
    int base = inst * SEQ;
    int tid  = threadIdx.x;

    __shared__ float qs[SEQ][HDIM], ks[SEQ][HDIM], vs[SEQ][HDIM];
    __shared__ float sc[SEQ][SEQ], ps[SEQ][SEQ];

    for (int idx = tid; idx < SEQ * HDIM; idx += 192) {
        int s = idx >> 6, d = idx & 63;
        size_t g = (size_t)(base + s) * EMB + h * HDIM + d;
        qs[s][d] = q[g];
        ks[s][d] = k[g];
        vs[s][d] = v[g];
    }
    __syncthreads();

    if (tid < SEQ * SEQ) {
        int i = tid / SEQ, j = tid % SEQ;
        float a = 0.0f;
#pragma unroll
        for (int d = 0; d < HDIM; ++d) a += qs[i][d] * ks[j][d];
        sc[i][j] = a * 0.125f;
    }
    __syncthreads();

    if (tid < SEQ) {
        float mx = -1e30f;
#pragma unroll
        for (int j = 0; j < SEQ; ++j) mx = fmaxf(mx, sc[tid][j]);
        float sum = 0.0f;
#pragma unroll
        for (int j = 0; j < SEQ; ++j) { float ev = expf(sc[tid][j] - mx); ps[tid][j] = ev; sum += ev; }
        float inv = 1.0f / sum;
#pragma unroll
        for (int j = 0; j < SEQ; ++j) ps[tid][j] *= inv;
    }
    __syncthreads();

    for (int idx = tid; idx < SEQ * HDIM; idx += 192) {
        int i = idx >> 6, d = idx & 63;
        float a = 0.0f;
#pragma unroll
        for (int j = 0; j < SEQ; ++j) a += ps[i][j] * vs[j][d];
        o[(size_t)(base + i) * EMB + h * HDIM + d] = a;
    }
}

// ---------------- output projection ----------------
__global__ __launch_bounds__(256) void outproj_kernel(
    const float* __restrict__ h, const float* __restrict__ Wout,
    const float* __restrict__ bout, float* __restrict__ logits)
{
    __shared__ float r0[256], r1[256], r2[256];
    int inst = blockIdx.x;
    int tid = threadIdx.x;
    const float* row = h + (size_t)inst * (SEQ * EMB);
    float a0 = 0, a1 = 0, a2 = 0;
    for (int kk = tid; kk < SEQ * EMB; kk += 256) {
        float x = row[kk];
        const float* w = Wout + kk * 3;
        a0 += x * w[0]; a1 += x * w[1]; a2 += x * w[2];
    }
    r0[tid] = a0; r1[tid] = a1; r2[tid] = a2;
    __syncthreads();
    for (int s = 128; s > 0; s >>= 1) {
        if (tid < s) { r0[tid] += r0[tid + s]; r1[tid] += r1[tid + s]; r2[tid] += r2[tid + s]; }
        __syncthreads();
    }
    if (tid == 0) {
        logits[inst * 3 + 0] = r0[0] + bout[0];
        logits[inst * 3 + 1] = r1[0] + bout[1];
        logits[inst * 3 + 2] = r2[0] + bout[2];
    }
}

// ---------------- greedy matching + loss: one block per lidx ----------------
__global__ __launch_bounds__(1024) void match_kernel(
    const float* __restrict__ logits, const float* __restrict__ targets,
    float* __restrict__ losses)
{
    extern __shared__ unsigned long long keys[];
    __shared__ int rowm[BATCH];
    __shared__ unsigned long long warpmin[32];
    __shared__ float red[1024];

    int lidx = blockIdx.x;
    int tid = threadIdx.x;
    int tref = 15 - lidx;
    const float* lg = logits + lidx * BATCH * 3;

    for (int e = tid; e < BATCH * BATCH; e += 1024) {
        int i = e >> 7, j = e & 127;
        float dx = lg[i * 3 + 0] - targets[(j * LSEQ + tref) * 3 + 0];
        float dy = lg[i * 3 + 1] - targets[(j * LSEQ + tref) * 3 + 1];
        float dz = lg[i * 3 + 2] - targets[(j * LSEQ + tref) * 3 + 2];
        float c = sqrtf(dx * dx + dy * dy + dz * dz + 1e-12f);
        keys[e] = ((unsigned long long)__float_as_uint(c) << 32) | (unsigned int)e;
    }
    __syncthreads();

    for (int r = 0; r < BATCH; ++r) {
        unsigned long long m = ~0ull;
        for (int e = tid; e < BATCH * BATCH; e += 1024) {
            unsigned long long kk = keys[e];
            m = (kk < m) ? kk : m;
        }
#pragma unroll
        for (int o = 16; o > 0; o >>= 1) {
            unsigned long long other = __shfl_down_sync(0xffffffffu, m, o);
            m = (other < m) ? other : m;
        }
        if ((tid & 31) == 0) warpmin[tid >> 5] = m;
        __syncthreads();
        if (tid < 32) {
            unsigned long long mm = warpmin[tid];
#pragma unroll
            for (int o = 16; o > 0; o >>= 1) {
                unsigned long long other = __shfl_down_sync(0xffffffffu, mm, o);
                mm = (other < mm) ? other : mm;
            }
            if (tid == 0) warpmin[0] = mm;
        }
        __syncthreads();
        unsigned long long best = warpmin[0];
        int e = (int)(best & 0xffffffffull);
        int bi = e >> 7, bj = e & 127;
        if (tid < BATCH) {
            keys[bi * BATCH + tid] = ~0ull;
            keys[tid * BATCH + bj] = ~0ull;
        }
        if (tid == 0) rowm[bi] = bj;
        __syncthreads();
    }

    float part = 0.0f;
    if (tid < BATCH * 3) {
        int i = tid / 3, c = tid % 3;
        float d = lg[rowm[i] * 3 + c] - targets[(i * LSEQ + tref) * 3 + c];
        part = d * d;
    }
    red[tid] = part;
    __syncthreads();
    for (int s = 512; s > 0; s >>= 1) {
        if (tid < s) red[tid] += red[tid + s];
        __syncthreads();
    }
    if (tid == 0) losses[lidx] = red[0] * (1.0f / (BATCH * 3));
}

__global__ void final_mean_kernel(const float* __restrict__ losses, float* __restrict__ out)
{
    if (threadIdx.x == 0 && blockIdx.x == 0) {
        float s = 0.0f;
        for (int i = 0; i < NLIDX; ++i) s += losses[i];
        out[0] = s * (1.0f / NLIDX);
    }
}

// ---------------- launch ----------------
extern "C" void kernel_launch(void* const* d_in, const int* in_sizes, int n_in,
                              void* d_out, int out_size)
{
    (void)in_sizes; (void)n_in; (void)out_size;
    const float* X    = (const float*)d_in[0];
    const float* tg   = (const float*)d_in[1];
    const float* om   = (const float*)d_in[2];
    const float* ph   = (const float*)d_in[3];
    const int*   pm   = (const int*)  d_in[4];
    const float* Wq   = (const float*)d_in[5];
    const float* bq   = (const float*)d_in[6];
    const float* Wk   = (const float*)d_in[7];
    const float* bk   = (const float*)d_in[8];
    const float* Wv   = (const float*)d_in[9];
    const float* bv   = (const float*)d_in[10];
    const float* Wo   = (const float*)d_in[11];
    const float* bo   = (const float*)d_in[12];
    const float* l1g  = (const float*)d_in[13];
    const float* l1b  = (const float*)d_in[14];
    const float* l2g  = (const float*)d_in[15];
    const float* l2b  = (const float*)d_in[16];
    const float* W1   = (const float*)d_in[17];
    const float* b1   = (const float*)d_in[18];
    const float* W2   = (const float*)d_in[19];
    const float* b2   = (const float*)d_in[20];
    const float* lfg  = (const float*)d_in[21];
    const float* lfb  = (const float*)d_in[22];
    const float* Wout = (const float*)d_in[23];
    const float* bout = (const float*)d_in[24];

    float *px, *phh, *pq, *pk, *pv, *po, *pmlp, *plog, *plos;
    __nv_bfloat16 *whi, *wlo;
    cudaGetSymbolAddress((void**)&px,   g_x);
    cudaGetSymbolAddress((void**)&phh,  g_h);
    cudaGetSymbolAddress((void**)&pq,   g_q);
    cudaGetSymbolAddress((void**)&pk,   g_k);
    cudaGetSymbolAddress((void**)&pv,   g_v);
    cudaGetSymbolAddress((void**)&po,   g_o);
    cudaGetSymbolAddress((void**)&pmlp, g_mlp);
    cudaGetSymbolAddress((void**)&plog, g_logits);
    cudaGetSymbolAddress((void**)&plos, g_losses);
    cudaGetSymbolAddress((void**)&whi,  g_whi);
    cudaGetSymbolAddress((void**)&wlo,  g_wlo);

    cudaFuncSetAttribute(match_kernel,
                         cudaFuncAttributeMaxDynamicSharedMemorySize, 131072);

    // -------- weight prep (transpose + bf16 split), runs every launch --------
    dim3 gE(EMB / 256, EMB / 16);      // (3, 48)   K=768, N=768
    dim3 gU(FF / 256,  EMB / 16);      // (12, 48)  K=768, N=3072
    dim3 gD(EMB / 256, FF / 16);       // (3, 192)  K=3072, N=768
    for (int l = 0; l < NL; ++l) {
        size_t base = (size_t)l * WLAYER;
        size_t wE   = (size_t)l * WQKV;
        size_t wF   = (size_t)l * WFFN;
        wprep_kernel<<<gE, 256>>>(Wq + wE, whi + base,            wlo + base,            EMB);
        wprep_kernel<<<gE, 256>>>(Wk + wE, whi + base + WQKV,     wlo + base + WQKV,     EMB);
        wprep_kernel<<<gE, 256>>>(Wv + wE, whi + base + 2 * WQKV, wlo + base + 2 * WQKV, EMB);
        wprep_kernel<<<gE, 256>>>(Wo + wE, whi + base + 3 * WQKV, wlo + base + 3 * WQKV, EMB);
        wprep_kernel<<<gU, 256>>>(W1 + wF, whi + base + 4 * WQKV, wlo + base + 4 * WQKV, FF);
        wprep_kernel<<<gD, 256>>>(W2 + wF, whi + base + 4 * WQKV + WFFN,
                                           wlo + base + 4 * WQKV + WFFN, EMB);
    }

    assemble_kernel<<<(TE + 255) / 256, 256>>>(X, tg, om, ph, pm, px);

    dim3 g768(EMB / 128, TOK / 128);   // (6, 180)
    dim3 g3072(FF / 128, TOK / 128);   // (24, 180)
    for (int l = 0; l < NL; ++l) {
        size_t base = (size_t)l * WLAYER;
        ln_kernel<<<TOK, 256>>>(px, phh, l1g + l * EMB, l1b + l * EMB);
        gemm_bf16x3<0><<<g768, 256>>>(phh, whi + base,            wlo + base,            bq + l * EMB, pq, TOK, EMB, EMB);
        gemm_bf16x3<0><<<g768, 256>>>(phh, whi + base + WQKV,     wlo + base + WQKV,     bk + l * EMB, pk, TOK, EMB, EMB);
        gemm_bf16x3<0><<<g768, 256>>>(phh, whi + base + 2 * WQKV, wlo + base + 2 * WQKV, bv + l * EMB, pv, TOK, EMB, EMB);
        attn_kernel<<<dim3(NLIDX * BATCH, HEADS), 192>>>(pq, pk, pv, po);
        gemm_bf16x3<1><<<g768, 256>>>(po, whi + base + 3 * WQKV,  wlo + base + 3 * WQKV, bo + l * EMB, px, TOK, EMB, EMB);
        ln_kernel<<<TOK, 256>>>(px, phh, l2g + l * EMB, l2b + l * EMB);
        gemm_bf16x3<2><<<g3072, 256>>>(phh, whi + base + 4 * WQKV, wlo + base + 4 * WQKV, b1 + l * FF, pmlp, TOK, FF, EMB);
        gemm_bf16x3<1><<<g768, 256>>>(pmlp, whi + base + 4 * WQKV + WFFN,
                                      wlo + base + 4 * WQKV + WFFN, b2 + l * EMB, px, TOK, EMB, FF);
    }
    ln_kernel<<<TOK, 256>>>(px, phh, lfg, lfb);
    outproj_kernel<<<NLIDX * BATCH, 256>>>(phh, Wout, bout, plog);
    match_kernel<<<NLIDX, 1024, 131072>>>(plog, tg, plos);
    final_mean_kernel<<<1, 32>>>(plos, (float*)d_out);
}

// round 9
// speedup vs baseline: 1.9665x; 1.1706x over previous
#include <cuda_runtime.h>
#include <cuda_bf16.h>
#include <math.h>
#include <stdint.h>

// ---------------- problem constants ----------------
#define BATCH  128
#define LSEQ   16
#define EMB    768
#define DHALF  384
#define HEADS  12
#define HDIM   64
#define NL     6
#define SEQ    12
#define NLIDX  15
#define FF     3072
#define TOK    (NLIDX * BATCH * SEQ)        // 23040
#define TE     (TOK * EMB)                  // 17694720

#define WQKV   (EMB * EMB)                  // 589824
#define WFFN   (EMB * FF)                   // 2359296
#define WLAYER (4 * WQKV + 2 * WFFN)        // 7077888
#define NQKV   (3 * EMB)                    // 2304

// GEMM tiling: 128x128 tile, BK=32, 2-stage cp.async pipeline
#define BM 128
#define BN 128
#define BKT 32
#define STAGE_BYTES 49152      // Ah 12288 + Al 12288 + Bh 12288 + Bl 12288
#define DSMEM_BYTES (2 * STAGE_BYTES)

// ---------------- scratch (device globals; no cudaMalloc allowed) ----------------
__device__ float g_x[TE];                          // fp32 residual stream
__device__ float g_qkv[(size_t)TOK * NQKV];        // fused qkv output (fp32)
__device__ __nv_bfloat16 g_ah[(size_t)TOK * EMB];  // 768-wide GEMM input hi
__device__ __nv_bfloat16 g_al[(size_t)TOK * EMB];  // 768-wide GEMM input lo
__device__ __nv_bfloat16 g_afh[(size_t)TOK * FF];  // 3072-wide GEMM input hi
__device__ __nv_bfloat16 g_afl[(size_t)TOK * FF];  // 3072-wide GEMM input lo
__device__ __nv_bfloat16 g_wh[(size_t)NL * WLAYER];// transposed weights hi  [N][K]
__device__ __nv_bfloat16 g_wl[(size_t)NL * WLAYER];// transposed weights lo
__device__ float g_bqkv[NL * NQKV];
__device__ float g_logits[NLIDX * BATCH * 3];
__device__ float g_losses[NLIDX];

// ---------------- helpers ----------------
static __device__ __forceinline__ unsigned int smem_u32(const void* p) {
    unsigned int a;
    asm("{ .reg .u64 t; cvta.to.shared.u64 t, %1; cvt.u32.u64 %0, t; }"
        : "=r"(a) : "l"(p));
    return a;
}
static __device__ __forceinline__ void cp16(unsigned int dst, const void* src) {
    asm volatile("cp.async.cg.shared.global [%0], [%1], 16;" :: "r"(dst), "l"(src));
}
static __device__ __forceinline__ void cp_commit() {
    asm volatile("cp.async.commit_group;" ::: "memory");
}
static __device__ __forceinline__ void cp_wait1() {
    asm volatile("cp.async.wait_group 1;" ::: "memory");
}
static __device__ __forceinline__ void cp_wait0() {
    asm volatile("cp.async.wait_group 0;" ::: "memory");
}
static __device__ __forceinline__ void ldsm4(unsigned int* r, unsigned int addr) {
    asm volatile("ldmatrix.sync.aligned.m8n8.x4.shared.b16 {%0,%1,%2,%3}, [%4];"
                 : "=r"(r[0]), "=r"(r[1]), "=r"(r[2]), "=r"(r[3]) : "r"(addr));
}
static __device__ __forceinline__ void mma_bf16(float* c, const unsigned int* a,
                                                unsigned int b0, unsigned int b1) {
    asm volatile(
        "mma.sync.aligned.m16n8k16.row.col.f32.bf16.bf16.f32 "
        "{%0,%1,%2,%3}, {%4,%5,%6,%7}, {%8,%9}, {%0,%1,%2,%3};"
        : "+f"(c[0]), "+f"(c[1]), "+f"(c[2]), "+f"(c[3])
        : "r"(a[0]), "r"(a[1]), "r"(a[2]), "r"(a[3]), "r"(b0), "r"(b1));
}
static __device__ __forceinline__ void split_bf16(float v, __nv_bfloat16& h, __nv_bfloat16& l) {
    h = __float2bfloat16_rn(v);
    l = __float2bfloat16_rn(v - __bfloat162float(h));
}
static __device__ __forceinline__ unsigned int pack_bf2(__nv_bfloat16 a, __nv_bfloat16 b) {
    __nv_bfloat162 p; p.x = a; p.y = b;
    return *reinterpret_cast<unsigned int*>(&p);
}

// ---------------- weight transpose+split: W[K][N] fp32 -> Wt[N][K] bf16 hi/lo ----------------
__global__ __launch_bounds__(256) void wtrans_kernel(
    const float* __restrict__ W, __nv_bfloat16* __restrict__ hi,
    __nv_bfloat16* __restrict__ lo, int K, int N)
{
    __shared__ float tile[32][33];
    int n0 = blockIdx.x * 32, k0 = blockIdx.y * 32;
    int tx = threadIdx.x & 31, ty = threadIdx.x >> 5;   // 32 x 8
#pragma unroll
    for (int j = 0; j < 4; ++j)
        tile[ty + j * 8][tx] = W[(size_t)(k0 + ty + j * 8) * N + n0 + tx];
    __syncthreads();
#pragma unroll
    for (int j = 0; j < 4; ++j) {
        int n = ty + j * 8;
        float v = tile[tx][n];
        __nv_bfloat16 h, l;
        split_bf16(v, h, l);
        size_t o = (size_t)(n0 + n) * K + k0 + tx;
        hi[o] = h;
        lo[o] = l;
    }
}

__global__ __launch_bounds__(256) void biascat_kernel(
    const float* __restrict__ bq, const float* __restrict__ bk,
    const float* __restrict__ bv, float* __restrict__ out)
{
    int idx = blockIdx.x * 256 + threadIdx.x;
    if (idx >= NL * NQKV) return;
    int l = idx / NQKV, n = idx % NQKV;
    float v;
    if (n < EMB) v = bq[l * EMB + n];
    else if (n < 2 * EMB) v = bk[l * EMB + n - EMB];
    else v = bv[l * EMB + n - 2 * EMB];
    out[idx] = v;
}

// ---------------- input assembly ----------------
__global__ __launch_bounds__(256) void assemble_kernel(
    const float* __restrict__ X, const float* __restrict__ targets,
    const float* __restrict__ omegas, const float* __restrict__ phases,
    const int* __restrict__ perms, float* __restrict__ xout)
{
    int idx = blockIdx.x * blockDim.x + threadIdx.x;
    if (idx >= TE) return;
    int e = idx % EMB;
    int t = idx / EMB;
    int s = t % SEQ;
    int b = (t / SEQ) % BATCH;
    int lidx = t / (SEQ * BATCH);
    int sb = perms[lidx * BATCH + b];

    float val;
    if (s < 3) {
        int c = s;
        int ti = (e < DHALF) ? (15 - lidx) : (14 - lidx);
        int d  = (e < DHALF) ? e : (e - DHALF);
        float xv = X[(sb * LSEQ + ti) * 3 + c];
        val = cosf(xv * omegas[c * DHALF + d] + phases[c * DHALF + d]);
    } else if (s < 6) {
        int c = s - 3;
        int ti = (16 - lidx) % 16;
        val = targets[(sb * LSEQ + ti) * 3 + c];
    } else {
        val = (float)(15 - lidx);
    }
    xout[idx] = val;
}

// ---------------- layernorm with bf16 hi/lo split output ----------------
__global__ __launch_bounds__(256) void ln_split_kernel(
    const float* __restrict__ in, __nv_bfloat16* __restrict__ oh,
    __nv_bfloat16* __restrict__ ol, const float* __restrict__ gam,
    const float* __restrict__ bet)
{
    __shared__ float red[256];
    __shared__ float s_mu, s_rs;
    int t = blockIdx.x;
    int tid = threadIdx.x;
    const float* x = in + (size_t)t * EMB;

    float v0 = x[tid], v1 = x[tid + 256], v2 = x[tid + 512];
    red[tid] = v0 + v1 + v2;
    __syncthreads();
    for (int s = 128; s > 0; s >>= 1) {
        if (tid < s) red[tid] += red[tid + s];
        __syncthreads();
    }
    if (tid == 0) s_mu = red[0] * (1.0f / EMB);
    __syncthreads();
    float mu = s_mu;
    float d0 = v0 - mu, d1 = v1 - mu, d2 = v2 - mu;
    red[tid] = d0 * d0 + d1 * d1 + d2 * d2;
    __syncthreads();
    for (int s = 128; s > 0; s >>= 1) {
        if (tid < s) red[tid] += red[tid + s];
        __syncthreads();
    }
    if (tid == 0) s_rs = rsqrtf(red[0] * (1.0f / EMB) + 1e-3f);
    __syncthreads();
    float rs = s_rs;
    size_t base = (size_t)t * EMB;
#pragma unroll
    for (int j = 0; j < 3; ++j) {
        int e = tid + j * 256;
        float d = (j == 0 ? d0 : (j == 1 ? d1 : d2));
        float r = d * rs * gam[e] + bet[e];
        __nv_bfloat16 h, l;
        split_bf16(r, h, l);
        oh[base + e] = h;
        ol[base + e] = l;
    }
}

// ---------------- bf16x3 mma.sync GEMM, cp.async double-buffered ----------------
// C[M, Ntot] = A[M, K] @ Wt[Ntot, K]^T, all operands pre-split bf16 hi/lo.
// Tile 128x128, BK=32 (2 k16 chunks), 2 stages. 8 warps as 2(m) x 4(n), warp 64x32.
// Stage layout (byte offsets): Ah 0, Al 12288, Bh 24576, Bl 36864.
//   each sub-tile: [2 chunks][128 rows][24 halves(48B, 32B data + 16B pad)]
// EPI 0: Cf = acc + bias ; 1: Cf += acc + bias ; 2: Ch/Cl = split(relu(acc + bias))
template <int EPI>
__global__ __launch_bounds__(256) void gemm_mma(
    const __nv_bfloat16* __restrict__ Ah, const __nv_bfloat16* __restrict__ Al,
    const __nv_bfloat16* __restrict__ Bh, const __nv_bfloat16* __restrict__ Bl,
    const float* __restrict__ bias, float* __restrict__ Cf,
    __nv_bfloat16* __restrict__ Ch, __nv_bfloat16* __restrict__ Cl,
    int Ntot, int K)
{
    extern __shared__ __align__(16) char dsm[];
    const int t = threadIdx.x;
    const int lane = t & 31, wid = t >> 5;
    const int wm = wid >> 2, wn = wid & 3;
    const int row0 = blockIdx.y * BM, col0 = blockIdx.x * BN;
    const unsigned int smem = smem_u32(dsm);

    float acc[4][4][4];
#pragma unroll
    for (int i = 0; i < 4; ++i)
#pragma unroll
        for (int j = 0; j < 4; ++j)
#pragma unroll
            for (int k = 0; k < 4; ++k) acc[i][j][k] = 0.0f;

    // cp.async mapping: c2 = t&3 -> (seg, chunk) covering 64B contiguous global
    const int seg   = t & 1;
    const int chunk = (t >> 1) & 1;
    const int rr    = t >> 2;                    // 0..63
    const int koff0 = chunk * 16 + seg * 8;
    const unsigned int dst_base = smem + chunk * 6144 + seg * 16;

    auto load_stage = [&](int kt, int stg) {
        unsigned int sb = dst_base + stg * STAGE_BYTES;
        int koff = kt * BKT + koff0;
#pragma unroll
        for (int i = 0; i < 8; ++i) {
            int ab = i >> 2, hl = (i >> 1) & 1, rh = i & 1;
            int r = rh * 64 + rr;
            const __nv_bfloat16* src;
            if (ab == 0) src = (hl ? Al : Ah) + (size_t)(row0 + r) * K + koff;
            else         src = (hl ? Bl : Bh) + (size_t)(col0 + r) * K + koff;
            cp16(sb + ab * 24576 + hl * 12288 + r * 48, src);
        }
        cp_commit();
    };

    // ldmatrix base addresses (proven layout from round 7)
    const int arow  = wm * 64 + (lane & 15);
    const int abyte = (lane >> 4) << 4;
    const unsigned int aHb = smem + arow * 48 + abyte;
    const int brow  = wn * 32 + (lane & 7) + ((lane >> 4) << 3);
    const int bbyte = ((lane >> 3) & 1) << 4;
    const unsigned int bHb = smem + 24576 + brow * 48 + bbyte;

    const int nst = K / BKT;
    load_stage(0, 0);
    if (nst > 1) load_stage(1, 1);

    for (int st = 0; st < nst; ++st) {
        if (st + 1 < nst) cp_wait1(); else cp_wait0();
        __syncthreads();
        unsigned int so = (st & 1) * STAGE_BYTES;
#pragma unroll
        for (int ch = 0; ch < 2; ++ch) {
            unsigned int co = so + ch * 6144;
            unsigned int Bfh[2][4], Bfl[2][4];
            ldsm4(Bfh[0], bHb + co);
            ldsm4(Bfh[1], bHb + co + 16 * 48);
            ldsm4(Bfl[0], bHb + co + 12288);
            ldsm4(Bfl[1], bHb + co + 12288 + 16 * 48);
#pragma unroll
            for (int mi = 0; mi < 4; ++mi) {
                unsigned int Afh[4], Afl[4];
                ldsm4(Afh, aHb + co + mi * (16 * 48));
                ldsm4(Afl, aHb + co + 12288 + mi * (16 * 48));
#pragma unroll
                for (int p = 0; p < 2; ++p)
#pragma unroll
                    for (int q = 0; q < 2; ++q) {
                        float* c = acc[mi][p * 2 + q];
                        mma_bf16(c, Afh, Bfh[p][2 * q], Bfh[p][2 * q + 1]);
                        mma_bf16(c, Afh, Bfl[p][2 * q], Bfl[p][2 * q + 1]);
                        mma_bf16(c, Afl, Bfh[p][2 * q], Bfh[p][2 * q + 1]);
                    }
            }
        }
        if (st + 2 < nst) {
            __syncthreads();
            load_stage(st + 2, st & 1);
        }
    }

    // ---- epilogue ----
    const int rbase = row0 + wm * 64 + (lane >> 2);
    const int cbase = col0 + wn * 32 + (lane & 3) * 2;
#pragma unroll
    for (int ni = 0; ni < 4; ++ni) {
        int cb = cbase + ni * 8;
        float2 bi = *(const float2*)&bias[cb];
#pragma unroll
        for (int mi = 0; mi < 4; ++mi) {
            float* c = acc[mi][ni];
            size_t o0 = (size_t)(rbase + mi * 16) * Ntot + cb;
            size_t o1 = o0 + (size_t)8 * Ntot;
            if (EPI == 2) {
                float v00 = fmaxf(c[0] + bi.x, 0.0f), v01 = fmaxf(c[1] + bi.y, 0.0f);
                float v10 = fmaxf(c[2] + bi.x, 0.0f), v11 = fmaxf(c[3] + bi.y, 0.0f);
                __nv_bfloat16 h00, l00, h01, l01, h10, l10, h11, l11;
                split_bf16(v00, h00, l00);
                split_bf16(v01, h01, l01);
                split_bf16(v10, h10, l10);
                split_bf16(v11, h11, l11);
                *(unsigned int*)&Ch[o0] = pack_bf2(h00, h01);
                *(unsigned int*)&Cl[o0] = pack_bf2(l00, l01);
                *(unsigned int*)&Ch[o1] = pack_bf2(h10, h11);
                *(unsigned int*)&Cl[o1] = pack_bf2(l10, l11);
            } else {
                float2 v0 = make_float2(c[0] + bi.x, c[1] + bi.y);
                float2 v1 = make_float2(c[2] + bi.x, c[3] + bi.y);
                if (EPI == 1) {
                    float2 p0 = *(float2*)&Cf[o0], p1 = *(float2*)&Cf[o1];
                    v0.x += p0.x; v0.y += p0.y;
                    v1.x += p1.x; v1.y += p1.y;
                }
                *(float2*)&Cf[o0] = v0;
                *(float2*)&Cf[o1] = v1;
            }
        }
    }
}

// ---------------- attention: reads fused qkv (stride 2304), writes hi/lo o ----------------
__global__ __launch_bounds__(192) void attn_kernel(
    const float* __restrict__ qkv, __nv_bfloat16* __restrict__ oh,
    __nv_bfloat16* __restrict__ ol)
{
    int inst = blockIdx.x;
    int h    = blockIdx.y;
    int base = inst * SEQ;
    int tid  = threadIdx.x;

    __shared__ float qs[SEQ][HDIM], ks[SEQ][HDIM], vs[SEQ][HDIM];
    __shared__ float sc[SEQ][SEQ], ps[SEQ][SEQ];

    for (int idx = tid; idx < SEQ * HDIM; idx += 192) {
        int s = idx >> 6, d = idx & 63;
        size_t g = (size_t)(base + s) * NQKV + h * HDIM + d;
        qs[s][d] = qkv[g];
        ks[s][d] = qkv[g + EMB];
        vs[s][d] = qkv[g + 2 * EMB];
    }
    __syncthreads();

    if (tid < SEQ * SEQ) {
        int i = tid / SEQ, j = tid % SEQ;
        float a = 0.0f;
#pragma unroll
        for (int d = 0; d < HDIM; ++d) a += qs[i][d] * ks[j][d];
        sc[i][j] = a * 0.125f;
    }
    __syncthreads();

    if (tid < SEQ) {
        float mx = -1e30f;
#pragma unroll
        for (int j = 0; j < SEQ; ++j) mx = fmaxf(mx, sc[tid][j]);
        float sum = 0.0f;
#pragma unroll
        for (int j = 0; j < SEQ; ++j) { float ev = expf(sc[tid][j] - mx); ps[tid][j] = ev; sum += ev; }
        float inv = 1.0f / sum;
#pragma unroll
        for (int j = 0; j < SEQ; ++j) ps[tid][j] *= inv;
    }
    __syncthreads();

    for (int idx = tid; idx < SEQ * HDIM; idx += 192) {
        int i = idx >> 6, d = idx & 63;
        float a = 0.0f;
#pragma unroll
        for (int j = 0; j < SEQ; ++j) a += ps[i][j] * vs[j][d];
        __nv_bfloat16 hh, ll;
        split_bf16(a, hh, ll);
        size_t g = (size_t)(base + i) * EMB + h * HDIM + d;
        oh[g] = hh;
        ol[g] = ll;
    }
}

// ---------------- output projection (reads hi+lo reconstructed) ----------------
__global__ __launch_bounds__(256) void outproj_kernel(
    const __nv_bfloat16* __restrict__ hh, const __nv_bfloat16* __restrict__ hl,
    const float* __restrict__ Wout, const float* __restrict__ bout,
    float* __restrict__ logits)
{
    __shared__ float r0[256], r1[256], r2[256];
    int inst = blockIdx.x;
    int tid = threadIdx.x;
    size_t base = (size_t)inst * (SEQ * EMB);
    float a0 = 0, a1 = 0, a2 = 0;
    for (int kk = tid; kk < SEQ * EMB; kk += 256) {
        float x = __bfloat162float(hh[base + kk]) + __bfloat162float(hl[base + kk]);
        const float* w = Wout + kk * 3;
        a0 += x * w[0]; a1 += x * w[1]; a2 += x * w[2];
    }
    r0[tid] = a0; r1[tid] = a1; r2[tid] = a2;
    __syncthreads();
    for (int s = 128; s > 0; s >>= 1) {
        if (tid < s) { r0[tid] += r0[tid + s]; r1[tid] += r1[tid + s]; r2[tid] += r2[tid + s]; }
        __syncthreads();
    }
    if (tid == 0) {
        logits[inst * 3 + 0] = r0[0] + bout[0];
        logits[inst * 3 + 1] = r1[0] + bout[1];
        logits[inst * 3 + 2] = r2[0] + bout[2];
    }
}

// ---------------- greedy matching + loss ----------------
__global__ __launch_bounds__(1024) void match_kernel(
    const float* __restrict__ logits, const float* __restrict__ targets,
    float* __restrict__ losses)
{
    extern __shared__ unsigned long long keys[];
    __shared__ int rowm[BATCH];
    __shared__ unsigned long long warpmin[32];
    __shared__ float red[1024];

    int lidx = blockIdx.x;
    int tid = threadIdx.x;
    int tref = 15 - lidx;
    const float* lg = logits + lidx * BATCH * 3;

    for (int e = tid; e < BATCH * BATCH; e += 1024) {
        int i = e >> 7, j = e & 127;
        float dx = lg[i * 3 + 0] - targets[(j * LSEQ + tref) * 3 + 0];
        float dy = lg[i * 3 + 1] - targets[(j * LSEQ + tref) * 3 + 1];
        float dz = lg[i * 3 + 2] - targets[(j * LSEQ + tref) * 3 + 2];
        float c = sqrtf(dx * dx + dy * dy + dz * dz + 1e-12f);
        keys[e] = ((unsigned long long)__float_as_uint(c) << 32) | (unsigned int)e;
    }
    __syncthreads();

    for (int r = 0; r < BATCH; ++r) {
        unsigned long long m = ~0ull;
        for (int e = tid; e < BATCH * BATCH; e += 1024) {
            unsigned long long kk = keys[e];
            m = (kk < m) ? kk : m;
        }
#pragma unroll
        for (int o = 16; o > 0; o >>= 1) {
            unsigned long long other = __shfl_down_sync(0xffffffffu, m, o);
            m = (other < m) ? other : m;
        }
        if ((tid & 31) == 0) warpmin[tid >> 5] = m;
        __syncthreads();
        if (tid < 32) {
            unsigned long long mm = warpmin[tid];
#pragma unroll
            for (int o = 16; o > 0; o >>= 1) {
                unsigned long long other = __shfl_down_sync(0xffffffffu, mm, o);
                mm = (other < mm) ? other : mm;
            }
            if (tid == 0) warpmin[0] = mm;
        }
        __syncthreads();
        unsigned long long best = warpmin[0];
        int e = (int)(best & 0xffffffffull);
        int bi = e >> 7, bj = e & 127;
        if (tid < BATCH) {
            keys[bi * BATCH + tid] = ~0ull;
            keys[tid * BATCH + bj] = ~0ull;
        }
        if (tid == 0) rowm[bi] = bj;
        __syncthreads();
    }

    float part = 0.0f;
    if (tid < BATCH * 3) {
        int i = tid / 3, c = tid % 3;
        float d = lg[rowm[i] * 3 + c] - targets[(i * LSEQ + tref) * 3 + c];
        part = d * d;
    }
    red[tid] = part;
    __syncthreads();
    for (int s = 512; s > 0; s >>= 1) {
        if (tid < s) red[tid] += red[tid + s];
        __syncthreads();
    }
    if (tid == 0) losses[lidx] = red[0] * (1.0f / (BATCH * 3));
}

__global__ void final_mean_kernel(const float* __restrict__ losses, float* __restrict__ out)
{
    if (threadIdx.x == 0 && blockIdx.x == 0) {
        float s = 0.0f;
        for (int i = 0; i < NLIDX; ++i) s += losses[i];
        out[0] = s * (1.0f / NLIDX);
    }
}

// ---------------- launch ----------------
extern "C" void kernel_launch(void* const* d_in, const int* in_sizes, int n_in,
                              void* d_out, int out_size)
{
    (void)in_sizes; (void)n_in; (void)out_size;
    const float* X    = (const float*)d_in[0];
    const float* tg   = (const float*)d_in[1];
    const float* om   = (const float*)d_in[2];
    const float* ph   = (const float*)d_in[3];
    const int*   pm   = (const int*)  d_in[4];
    const float* Wq   = (const float*)d_in[5];
    const float* bq   = (const float*)d_in[6];
    const float* Wk   = (const float*)d_in[7];
    const float* bk   = (const float*)d_in[8];
    const float* Wv   = (const float*)d_in[9];
    const float* bv   = (const float*)d_in[10];
    const float* Wo   = (const float*)d_in[11];
    const float* bo   = (const float*)d_in[12];
    const float* l1g  = (const float*)d_in[13];
    const float* l1b  = (const float*)d_in[14];
    const float* l2g  = (const float*)d_in[15];
    const float* l2b  = (const float*)d_in[16];
    const float* W1   = (const float*)d_in[17];
    const float* b1   = (const float*)d_in[18];
    const float* W2   = (const float*)d_in[19];
    const float* b2   = (const float*)d_in[20];
    const float* lfg  = (const float*)d_in[21];
    const float* lfb  = (const float*)d_in[22];
    const float* Wout = (const float*)d_in[23];
    const float* bout = (const float*)d_in[24];

    float *px, *pqkv, *pbqkv, *plog, *plos;
    __nv_bfloat16 *pah, *pal, *pafh, *pafl, *pwh, *pwl;
    cudaGetSymbolAddress((void**)&px,    g_x);
    cudaGetSymbolAddress((void**)&pqkv,  g_qkv);
    cudaGetSymbolAddress((void**)&pbqkv, g_bqkv);
    cudaGetSymbolAddress((void**)&plog,  g_logits);
    cudaGetSymbolAddress((void**)&plos,  g_losses);
    cudaGetSymbolAddress((void**)&pah,   g_ah);
    cudaGetSymbolAddress((void**)&pal,   g_al);
    cudaGetSymbolAddress((void**)&pafh,  g_afh);
    cudaGetSymbolAddress((void**)&pafl,  g_afl);
    cudaGetSymbolAddress((void**)&pwh,   g_wh);
    cudaGetSymbolAddress((void**)&pwl,   g_wl);

    cudaFuncSetAttribute(match_kernel, cudaFuncAttributeMaxDynamicSharedMemorySize, 131072);
    cudaFuncSetAttribute(gemm_mma<0>, cudaFuncAttributeMaxDynamicSharedMemorySize, DSMEM_BYTES);
    cudaFuncSetAttribute(gemm_mma<1>, cudaFuncAttributeMaxDynamicSharedMemorySize, DSMEM_BYTES);
    cudaFuncSetAttribute(gemm_mma<2>, cudaFuncAttributeMaxDynamicSharedMemorySize, DSMEM_BYTES);

    // weight prep: transpose+split into [N][K] arenas
    // layer arena: [0: qkv Wt 2304x768][3*WQKV: proj Wt 768x768]
    //              [4*WQKV: W1t 3072x768][4*WQKV+WFFN: W2t 768x3072]
    for (int l = 0; l < NL; ++l) {
        size_t base = (size_t)l * WLAYER;
        size_t wE   = (size_t)l * WQKV;
        size_t wF   = (size_t)l * WFFN;
        dim3 gSq(EMB / 32, EMB / 32);
        wtrans_kernel<<<gSq, 256>>>(Wq + wE, pwh + base,                     pwl + base,                     EMB, EMB);
        wtrans_kernel<<<gSq, 256>>>(Wk + wE, pwh + base + (size_t)WQKV,     pwl + base + (size_t)WQKV,     EMB, EMB);
        wtrans_kernel<<<gSq, 256>>>(Wv + wE, pwh + base + (size_t)2 * WQKV, pwl + base + (size_t)2 * WQKV, EMB, EMB);
        wtrans_kernel<<<gSq, 256>>>(Wo + wE, pwh + base + (size_t)3 * WQKV, pwl + base + (size_t)3 * WQKV, EMB, EMB);
        wtrans_kernel<<<dim3(FF / 32, EMB / 32), 256>>>(W1 + wF, pwh + base + (size_t)4 * WQKV,
                                                        pwl + base + (size_t)4 * WQKV, EMB, FF);
        wtrans_kernel<<<dim3(EMB / 32, FF / 32), 256>>>(W2 + wF, pwh + base + (size_t)4 * WQKV + WFFN,
                                                        pwl + base + (size_t)4 * WQKV + WFFN, FF, EMB);
    }
    biascat_kernel<<<(NL * NQKV + 255) / 256, 256>>>(bq, bk, bv, pbqkv);

    assemble_kernel<<<(TE + 255) / 256, 256>>>(X, tg, om, ph, pm, px);

    dim3 gQKV(NQKV / BN, TOK / BM);   // (18, 180)
    dim3 gE(EMB / BN, TOK / BM);      // (6, 180)
    dim3 gF(FF / BN, TOK / BM);       // (24, 180)
    for (int l = 0; l < NL; ++l) {
        size_t base = (size_t)l * WLAYER;
        ln_split_kernel<<<TOK, 256>>>(px, pah, pal, l1g + l * EMB, l1b + l * EMB);
        gemm_mma<0><<<gQKV, 256, DSMEM_BYTES>>>(pah, pal, pwh + base, pwl + base,
                                                pbqkv + l * NQKV, pqkv, pafh, pafl, NQKV, EMB);
        attn_kernel<<<dim3(NLIDX * BATCH, HEADS), 192>>>(pqkv, pah, pal);
        gemm_mma<1><<<gE, 256, DSMEM_BYTES>>>(pah, pal, pwh + base + (size_t)3 * WQKV,
                                              pwl + base + (size_t)3 * WQKV,
                                              bo + l * EMB, px, pafh, pafl, EMB, EMB);
        ln_split_kernel<<<TOK, 256>>>(px, pah, pal, l2g + l * EMB, l2b + l * EMB);
        gemm_mma<2><<<gF, 256, DSMEM_BYTES>>>(pah, pal, pwh + base + (size_t)4 * WQKV,
                                              pwl + base + (size_t)4 * WQKV,
                                              b1 + l * FF, px, pafh, pafl, FF, EMB);
        gemm_mma<1><<<gE, 256, DSMEM_BYTES>>>(pafh, pafl, pwh + base + (size_t)4 * WQKV + WFFN,
                                              pwl + base + (size_t)4 * WQKV + WFFN,
                                              b2 + l * EMB, px, pafh, pafl, EMB, FF);
    }
    ln_split_kernel<<<TOK, 256>>>(px, pah, pal, lfg, lfb);
    outproj_kernel<<<NLIDX * BATCH, 256>>>(pah, pal, Wout, bout, plog);
    match_kernel<<<NLIDX, 1024, 131072>>>(plog, tg, plos);
    final_mean_kernel<<<1, 32>>>(plos, (float*)d_out);
}

// round 10
// speedup vs baseline: 2.1815x; 1.1094x over previous
#include <cuda_runtime.h>
#include <cuda_bf16.h>
#include <math.h>
#include <stdint.h>

// ---------------- problem constants ----------------
#define BATCH  128
#define LSEQ   16
#define EMB    768
#define DHALF  384
#define HEADS  12
#define HDIM   64
#define NL     6
#define SEQ    12
#define NLIDX  15
#define FF     3072
#define TOK    (NLIDX * BATCH * SEQ)        // 23040
#define TE     (TOK * EMB)                  // 17694720

#define WQKV   (EMB * EMB)                  // 589824
#define WFFN   (EMB * FF)                   // 2359296
#define WLAYER (4 * WQKV + 2 * WFFN)        // 7077888
#define NQKV   (3 * EMB)                    // 2304

// GEMM tiling: 128x128 tile, BK=32, 2-stage cp.async pipeline
#define BM 128
#define BN 128
#define BKT 32
#define STAGE_BYTES 49152      // Ah 12288 + Al 12288 + Bh 12288 + Bl 12288
#define DSMEM_BYTES (2 * STAGE_BYTES)

// ---------------- scratch (device globals; no cudaMalloc allowed) ----------------
__device__ float g_x[TE];                          // fp32 residual stream
__device__ float g_qkv[(size_t)TOK * NQKV];        // fused qkv output (fp32)
__device__ __nv_bfloat16 g_ah[(size_t)TOK * EMB];  // 768-wide GEMM input hi
__device__ __nv_bfloat16 g_al[(size_t)TOK * EMB];  // 768-wide GEMM input lo
__device__ __nv_bfloat16 g_afh[(size_t)TOK * FF];  // 3072-wide GEMM input hi
__device__ __nv_bfloat16 g_afl[(size_t)TOK * FF];  // 3072-wide GEMM input lo
__device__ __nv_bfloat16 g_wh[(size_t)NL * WLAYER];// transposed weights hi  [N][K]
__device__ __nv_bfloat16 g_wl[(size_t)NL * WLAYER];// transposed weights lo
__device__ float g_bqkv[NL * NQKV];
__device__ float g_logits[NLIDX * BATCH * 3];
__device__ float g_losses[NLIDX];

// ---------------- helpers ----------------
static __device__ __forceinline__ unsigned int smem_u32(const void* p) {
    unsigned int a;
    asm("{ .reg .u64 t; cvta.to.shared.u64 t, %1; cvt.u32.u64 %0, t; }"
        : "=r"(a) : "l"(p));
    return a;
}
static __device__ __forceinline__ void cp16(unsigned int dst, const void* src) {
    asm volatile("cp.async.cg.shared.global [%0], [%1], 16;" :: "r"(dst), "l"(src));
}
static __device__ __forceinline__ void cp_commit() {
    asm volatile("cp.async.commit_group;" ::: "memory");
}
static __device__ __forceinline__ void cp_wait1() {
    asm volatile("cp.async.wait_group 1;" ::: "memory");
}
static __device__ __forceinline__ void cp_wait0() {
    asm volatile("cp.async.wait_group 0;" ::: "memory");
}
static __device__ __forceinline__ void ldsm4(unsigned int* r, unsigned int addr) {
    asm volatile("ldmatrix.sync.aligned.m8n8.x4.shared.b16 {%0,%1,%2,%3}, [%4];"
                 : "=r"(r[0]), "=r"(r[1]), "=r"(r[2]), "=r"(r[3]) : "r"(addr));
}
static __device__ __forceinline__ void mma_bf16(float* c, const unsigned int* a,
                                                unsigned int b0, unsigned int b1) {
    asm volatile(
        "mma.sync.aligned.m16n8k16.row.col.f32.bf16.bf16.f32 "
        "{%0,%1,%2,%3}, {%4,%5,%6,%7}, {%8,%9}, {%0,%1,%2,%3};"
        : "+f"(c[0]), "+f"(c[1]), "+f"(c[2]), "+f"(c[3])
        : "r"(a[0]), "r"(a[1]), "r"(a[2]), "r"(a[3]), "r"(b0), "r"(b1));
}
static __device__ __forceinline__ void split_bf16(float v, __nv_bfloat16& h, __nv_bfloat16& l) {
    h = __float2bfloat16_rn(v);
    l = __float2bfloat16_rn(v - __bfloat162float(h));
}
static __device__ __forceinline__ unsigned int pack_bf2(__nv_bfloat16 a, __nv_bfloat16 b) {
    __nv_bfloat162 p; p.x = a; p.y = b;
    return *reinterpret_cast<unsigned int*>(&p);
}

// ---------------- batched weight transpose+split ----------------
// Square matrices (Wq, Wk, Wv, Wo): blockIdx.z = l*4 + m
__global__ __launch_bounds__(256) void wtrans_sq_kernel(
    const float* __restrict__ Wq, const float* __restrict__ Wk,
    const float* __restrict__ Wv, const float* __restrict__ Wo,
    __nv_bfloat16* __restrict__ hi, __nv_bfloat16* __restrict__ lo)
{
    __shared__ float tile[32][33];
    int z = blockIdx.z;
    int l = z >> 2, m = z & 3;
    const float* W = (m == 0) ? Wq : (m == 1) ? Wk : (m == 2) ? Wv : Wo;
    W += (size_t)l * WQKV;
    size_t obase = (size_t)l * WLAYER + (size_t)m * WQKV;

    int n0 = blockIdx.x * 32, k0 = blockIdx.y * 32;
    int tx = threadIdx.x & 31, ty = threadIdx.x >> 5;
#pragma unroll
    for (int j = 0; j < 4; ++j)
        tile[ty + j * 8][tx] = W[(size_t)(k0 + ty + j * 8) * EMB + n0 + tx];
    __syncthreads();
#pragma unroll
    for (int j = 0; j < 4; ++j) {
        int n = ty + j * 8;
        float v = tile[tx][n];
        __nv_bfloat16 h, l2;
        split_bf16(v, h, l2);
        size_t o = obase + (size_t)(n0 + n) * EMB + k0 + tx;
        hi[o] = h;
        lo[o] = l2;
    }
}

// W1 (K=768, N=3072) all layers: blockIdx.z = l
__global__ __launch_bounds__(256) void wtrans_f1_kernel(
    const float* __restrict__ W1, __nv_bfloat16* __restrict__ hi,
    __nv_bfloat16* __restrict__ lo)
{
    __shared__ float tile[32][33];
    int l = blockIdx.z;
    const float* W = W1 + (size_t)l * WFFN;
    size_t obase = (size_t)l * WLAYER + (size_t)4 * WQKV;

    int n0 = blockIdx.x * 32, k0 = blockIdx.y * 32;
    int tx = threadIdx.x & 31, ty = threadIdx.x >> 5;
#pragma unroll
    for (int j = 0; j < 4; ++j)
        tile[ty + j * 8][tx] = W[(size_t)(k0 + ty + j * 8) * FF + n0 + tx];
    __syncthreads();
#pragma unroll
    for (int j = 0; j < 4; ++j) {
        int n = ty + j * 8;
        float v = tile[tx][n];
        __nv_bfloat16 h, l2;
        split_bf16(v, h, l2);
        size_t o = obase + (size_t)(n0 + n) * EMB + k0 + tx;
        hi[o] = h;
        lo[o] = l2;
    }
}

// W2 (K=3072, N=768) all layers: blockIdx.z = l
__global__ __launch_bounds__(256) void wtrans_f2_kernel(
    const float* __restrict__ W2, __nv_bfloat16* __restrict__ hi,
    __nv_bfloat16* __restrict__ lo)
{
    __shared__ float tile[32][33];
    int l = blockIdx.z;
    const float* W = W2 + (size_t)l * WFFN;
    size_t obase = (size_t)l * WLAYER + (size_t)4 * WQKV + WFFN;

    int n0 = blockIdx.x * 32, k0 = blockIdx.y * 32;
    int tx = threadIdx.x & 31, ty = threadIdx.x >> 5;
#pragma unroll
    for (int j = 0; j < 4; ++j)
        tile[ty + j * 8][tx] = W[(size_t)(k0 + ty + j * 8) * EMB + n0 + tx];
    __syncthreads();
#pragma unroll
    for (int j = 0; j < 4; ++j) {
        int n = ty + j * 8;
        float v = tile[tx][n];
        __nv_bfloat16 h, l2;
        split_bf16(v, h, l2);
        size_t o = obase + (size_t)(n0 + n) * FF + k0 + tx;
        hi[o] = h;
        lo[o] = l2;
    }
}

// ---------------- input assembly (+ fused qkv bias concat in tail blocks) ----------------
#define ASM_TOTAL (TE + NL * NQKV)
__global__ __launch_bounds__(256) void assemble_kernel(
    const float* __restrict__ X, const float* __restrict__ targets,
    const float* __restrict__ omegas, const float* __restrict__ phases,
    const int* __restrict__ perms, float* __restrict__ xout,
    const float* __restrict__ bq, const float* __restrict__ bk,
    const float* __restrict__ bv, float* __restrict__ bqkv)
{
    int idx = blockIdx.x * blockDim.x + threadIdx.x;
    if (idx >= ASM_TOTAL) return;
    if (idx >= TE) {
        int k = idx - TE;
        int l = k / NQKV, n = k % NQKV;
        float v;
        if (n < EMB) v = bq[l * EMB + n];
        else if (n < 2 * EMB) v = bk[l * EMB + n - EMB];
        else v = bv[l * EMB + n - 2 * EMB];
        bqkv[k] = v;
        return;
    }
    int e = idx % EMB;
    int t = idx / EMB;
    int s = t % SEQ;
    int b = (t / SEQ) % BATCH;
    int lidx = t / (SEQ * BATCH);
    int sb = perms[lidx * BATCH + b];

    float val;
    if (s < 3) {
        int c = s;
        int ti = (e < DHALF) ? (15 - lidx) : (14 - lidx);
        int d  = (e < DHALF) ? e : (e - DHALF);
        float xv = X[(sb * LSEQ + ti) * 3 + c];
        val = cosf(xv * omegas[c * DHALF + d] + phases[c * DHALF + d]);
    } else if (s < 6) {
        int c = s - 3;
        int ti = (16 - lidx) % 16;
        val = targets[(sb * LSEQ + ti) * 3 + c];
    } else {
        val = (float)(15 - lidx);
    }
    xout[idx] = val;
}

// ---------------- layernorm with bf16 hi/lo split output ----------------
__global__ __launch_bounds__(256) void ln_split_kernel(
    const float* __restrict__ in, __nv_bfloat16* __restrict__ oh,
    __nv_bfloat16* __restrict__ ol, const float* __restrict__ gam,
    const float* __restrict__ bet)
{
    __shared__ float red[256];
    __shared__ float s_mu, s_rs;
    int t = blockIdx.x;
    int tid = threadIdx.x;
    const float* x = in + (size_t)t * EMB;

    float v0 = x[tid], v1 = x[tid + 256], v2 = x[tid + 512];
    red[tid] = v0 + v1 + v2;
    __syncthreads();
    for (int s = 128; s > 0; s >>= 1) {
        if (tid < s) red[tid] += red[tid + s];
        __syncthreads();
    }
    if (tid == 0) s_mu = red[0] * (1.0f / EMB);
    __syncthreads();
    float mu = s_mu;
    float d0 = v0 - mu, d1 = v1 - mu, d2 = v2 - mu;
    red[tid] = d0 * d0 + d1 * d1 + d2 * d2;
    __syncthreads();
    for (int s = 128; s > 0; s >>= 1) {
        if (tid < s) red[tid] += red[tid + s];
        __syncthreads();
    }
    if (tid == 0) s_rs = rsqrtf(red[0] * (1.0f / EMB) + 1e-3f);
    __syncthreads();
    float rs = s_rs;
    size_t base = (size_t)t * EMB;
#pragma unroll
    for (int j = 0; j < 3; ++j) {
        int e = tid + j * 256;
        float d = (j == 0 ? d0 : (j == 1 ? d1 : d2));
        float r = d * rs * gam[e] + bet[e];
        __nv_bfloat16 h, l;
        split_bf16(r, h, l);
        oh[base + e] = h;
        ol[base + e] = l;
    }
}

// ---------------- bf16x3 mma.sync GEMM, cp.async double-buffered, 2 CTAs/SM ----------------
// C[M, Ntot] = A[M, K] @ Wt[Ntot, K]^T, all operands pre-split bf16 hi/lo.
// Tile 128x128, BK=32 (2 k16 chunks), 2 stages. 8 warps as 2(m) x 4(n), warp 64x32.
// EPI 0: Cf = acc + bias ; 1: Cf += acc + bias ; 2: Ch/Cl = split(relu(acc + bias))
template <int EPI>
__global__ __launch_bounds__(256, 2) void gemm_mma(
    const __nv_bfloat16* __restrict__ Ah, const __nv_bfloat16* __restrict__ Al,
    const __nv_bfloat16* __restrict__ Bh, const __nv_bfloat16* __restrict__ Bl,
    const float* __restrict__ bias, float* __restrict__ Cf,
    __nv_bfloat16* __restrict__ Ch, __nv_bfloat16* __restrict__ Cl,
    int Ntot, int K)
{
    extern __shared__ __align__(16) char dsm[];
    const int t = threadIdx.x;
    const int lane = t & 31, wid = t >> 5;
    const int wm = wid >> 2, wn = wid & 3;
    const int row0 = blockIdx.y * BM, col0 = blockIdx.x * BN;
    const unsigned int smem = smem_u32(dsm);

    float acc[4][4][4];
#pragma unroll
    for (int i = 0; i < 4; ++i)
#pragma unroll
        for (int j = 0; j < 4; ++j)
#pragma unroll
            for (int k = 0; k < 4; ++k) acc[i][j][k] = 0.0f;

    // cp.async mapping: (seg, chunk) covering 64B contiguous global per pair
    const int seg   = t & 1;
    const int chunk = (t >> 1) & 1;
    const int rr    = t >> 2;                    // 0..63
    const int koff0 = chunk * 16 + seg * 8;
    const unsigned int dst_base = smem + chunk * 6144 + seg * 16;

    auto load_stage = [&](int kt, int stg) {
        unsigned int sb = dst_base + stg * STAGE_BYTES;
        int koff = kt * BKT + koff0;
#pragma unroll
        for (int i = 0; i < 8; ++i) {
            int ab = i >> 2, hl = (i >> 1) & 1, rh = i & 1;
            int r = rh * 64 + rr;
            const __nv_bfloat16* src;
            if (ab == 0) src = (hl ? Al : Ah) + (size_t)(row0 + r) * K + koff;
            else         src = (hl ? Bl : Bh) + (size_t)(col0 + r) * K + koff;
            cp16(sb + ab * 24576 + hl * 12288 + r * 48, src);
        }
        cp_commit();
    };

    // ldmatrix base addresses
    const int arow  = wm * 64 + (lane & 15);
    const int abyte = (lane >> 4) << 4;
    const unsigned int aHb = smem + arow * 48 + abyte;
    const int brow  = wn * 32 + (lane & 7) + ((lane >> 4) << 3);
    const int bbyte = ((lane >> 3) & 1) << 4;
    const unsigned int bHb = smem + 24576 + brow * 48 + bbyte;

    const int nst = K / BKT;
    load_stage(0, 0);
    if (nst > 1) load_stage(1, 1);

    for (int st = 0; st < nst; ++st) {
        if (st + 1 < nst) cp_wait1(); else cp_wait0();
        __syncthreads();
        unsigned int so = (st & 1) * STAGE_BYTES;
#pragma unroll
        for (int ch = 0; ch < 2; ++ch) {
            unsigned int co = so + ch * 6144;
            unsigned int Bfh[2][4], Bfl[2][4];
            ldsm4(Bfh[0], bHb + co);
            ldsm4(Bfh[1], bHb + co + 16 * 48);
            ldsm4(Bfl[0], bHb + co + 12288);
            ldsm4(Bfl[1], bHb + co + 12288 + 16 * 48);
#pragma unroll
            for (int mi = 0; mi < 4; ++mi) {
                unsigned int Afh[4], Afl[4];
                ldsm4(Afh, aHb + co + mi * (16 * 48));
                ldsm4(Afl, aHb + co + 12288 + mi * (16 * 48));
#pragma unroll
                for (int p = 0; p < 2; ++p)
#pragma unroll
                    for (int q = 0; q < 2; ++q) {
                        float* c = acc[mi][p * 2 + q];
                        mma_bf16(c, Afh, Bfh[p][2 * q], Bfh[p][2 * q + 1]);
                        mma_bf16(c, Afh, Bfl[p][2 * q], Bfl[p][2 * q + 1]);
                        mma_bf16(c, Afl, Bfh[p][2 * q], Bfh[p][2 * q + 1]);
                    }
            }
        }
        if (st + 2 < nst) {
            __syncthreads();
            load_stage(st + 2, st & 1);
        }
    }

    // ---- epilogue ----
    const int rbase = row0 + wm * 64 + (lane >> 2);
    const int cbase = col0 + wn * 32 + (lane & 3) * 2;
#pragma unroll
    for (int ni = 0; ni < 4; ++ni) {
        int cb = cbase + ni * 8;
        float2 bi = *(const float2*)&bias[cb];
#pragma unroll
        for (int mi = 0; mi < 4; ++mi) {
            float* c = acc[mi][ni];
            size_t o0 = (size_t)(rbase + mi * 16) * Ntot + cb;
            size_t o1 = o0 + (size_t)8 * Ntot;
            if (EPI == 2) {
                float v00 = fmaxf(c[0] + bi.x, 0.0f), v01 = fmaxf(c[1] + bi.y, 0.0f);
                float v10 = fmaxf(c[2] + bi.x, 0.0f), v11 = fmaxf(c[3] + bi.y, 0.0f);
                __nv_bfloat16 h00, l00, h01, l01, h10, l10, h11, l11;
                split_bf16(v00, h00, l00);
                split_bf16(v01, h01, l01);
                split_bf16(v10, h10, l10);
                split_bf16(v11, h11, l11);
                *(unsigned int*)&Ch[o0] = pack_bf2(h00, h01);
                *(unsigned int*)&Cl[o0] = pack_bf2(l00, l01);
                *(unsigned int*)&Ch[o1] = pack_bf2(h10, h11);
                *(unsigned int*)&Cl[o1] = pack_bf2(l10, l11);
            } else {
                float2 v0 = make_float2(c[0] + bi.x, c[1] + bi.y);
                float2 v1 = make_float2(c[2] + bi.x, c[3] + bi.y);
                if (EPI == 1) {
                    float2 p0 = *(float2*)&Cf[o0], p1 = *(float2*)&Cf[o1];
                    v0.x += p0.x; v0.y += p0.y;
                    v1.x += p1.x; v1.y += p1.y;
                }
                *(float2*)&Cf[o0] = v0;
                *(float2*)&Cf[o1] = v1;
            }
        }
    }
}

// ---------------- attention: reads fused qkv (stride 2304), writes hi/lo o ----------------
__global__ __launch_bounds__(192) void attn_kernel(
    const float* __restrict__ qkv, __nv_bfloat16* __restrict__ oh,
    __nv_bfloat16* __restrict__ ol)
{
    int inst = blockIdx.x;
    int h    = blockIdx.y;
    int base = inst * SEQ;
    int tid  = threadIdx.x;

    __shared__ float qs[SEQ][HDIM], ks[SEQ][HDIM], vs[SEQ][HDIM];
    __shared__ float sc[SEQ][SEQ], ps[SEQ][SEQ];

    for (int idx = tid; idx < SEQ * HDIM; idx += 192) {
        int s = idx >> 6, d = idx & 63;
        size_t g = (size_t)(base + s) * NQKV + h * HDIM + d;
        qs[s][d] = qkv[g];
        ks[s][d] = qkv[g + EMB];
        vs[s][d] = qkv[g + 2 * EMB];
    }
    __syncthreads();

    if (tid < SEQ * SEQ) {
        int i = tid / SEQ, j = tid % SEQ;
        float a = 0.0f;
#pragma unroll
        for (int d = 0; d < HDIM; ++d) a += qs[i][d] * ks[j][d];
        sc[i][j] = a * 0.125f;
    }
    __syncthreads();

    if (tid < SEQ) {
        float mx = -1e30f;
#pragma unroll
        for (int j = 0; j < SEQ; ++j) mx = fmaxf(mx, sc[tid][j]);
        float sum = 0.0f;
#pragma unroll
        for (int j = 0; j < SEQ; ++j) { float ev = expf(sc[tid][j] - mx); ps[tid][j] = ev; sum += ev; }
        float inv = 1.0f / sum;
#pragma unroll
        for (int j = 0; j < SEQ; ++j) ps[tid][j] *= inv;
    }
    __syncthreads();

    for (int idx = tid; idx < SEQ * HDIM; idx += 192) {
        int i = idx >> 6, d = idx & 63;
        float a = 0.0f;
#pragma unroll
        for (int j = 0; j < SEQ; ++j) a += ps[i][j] * vs[j][d];
        __nv_bfloat16 hh, ll;
        split_bf16(a, hh, ll);
        size_t g = (size_t)(base + i) * EMB + h * HDIM + d;
        oh[g] = hh;
        ol[g] = ll;
    }
}

// ---------------- output projection (reads hi+lo reconstructed) ----------------
__global__ __launch_bounds__(256) void outproj_kernel(
    const __nv_bfloat16* __restrict__ hh, const __nv_bfloat16* __restrict__ hl,
    const float* __restrict__ Wout, const float* __restrict__ bout,
    float* __restrict__ logits)
{
    __shared__ float r0[256], r1[256], r2[256];
    int inst = blockIdx.x;
    int tid = threadIdx.x;
    size_t base = (size_t)inst * (SEQ * EMB);
    float a0 = 0, a1 = 0, a2 = 0;
    for (int kk = tid; kk < SEQ * EMB; kk += 256) {
        float x = __bfloat162float(hh[base + kk]) + __bfloat162float(hl[base + kk]);
        const float* w = Wout + kk * 3;
        a0 += x * w[0]; a1 += x * w[1]; a2 += x * w[2];
    }
    r0[tid] = a0; r1[tid] = a1; r2[tid] = a2;
    __syncthreads();
    for (int s = 128; s > 0; s >>= 1) {
        if (tid < s) { r0[tid] += r0[tid + s]; r1[tid] += r1[tid + s]; r2[tid] += r2[tid + s]; }
        __syncthreads();
    }
    if (tid == 0) {
        logits[inst * 3 + 0] = r0[0] + bout[0];
        logits[inst * 3 + 1] = r1[0] + bout[1];
        logits[inst * 3 + 2] = r2[0] + bout[2];
    }
}

// ---------------- greedy matching + loss ----------------
__global__ __launch_bounds__(1024) void match_kernel(
    const float* __restrict__ logits, const float* __restrict__ targets,
    float* __restrict__ losses)
{
    extern __shared__ unsigned long long keys[];
    __shared__ int rowm[BATCH];
    __shared__ unsigned long long warpmin[32];
    __shared__ float red[1024];

    int lidx = blockIdx.x;
    int tid = threadIdx.x;
    int tref = 15 - lidx;
    const float* lg = logits + lidx * BATCH * 3;

    for (int e = tid; e < BATCH * BATCH; e += 1024) {
        int i = e >> 7, j = e & 127;
        float dx = lg[i * 3 + 0] - targets[(j * LSEQ + tref) * 3 + 0];
        float dy = lg[i * 3 + 1] - targets[(j * LSEQ + tref) * 3 + 1];
        float dz = lg[i * 3 + 2] - targets[(j * LSEQ + tref) * 3 + 2];
        float c = sqrtf(dx * dx + dy * dy + dz * dz + 1e-12f);
        keys[e] = ((unsigned long long)__float_as_uint(c) << 32) | (unsigned int)e;
    }
    __syncthreads();

    for (int r = 0; r < BATCH; ++r) {
        unsigned long long m = ~0ull;
        for (int e = tid; e < BATCH * BATCH; e += 1024) {
            unsigned long long kk = keys[e];
            m = (kk < m) ? kk : m;
        }
#pragma unroll
        for (int o = 16; o > 0; o >>= 1) {
            unsigned long long other = __shfl_down_sync(0xffffffffu, m, o);
            m = (other < m) ? other : m;
        }
        if ((tid & 31) == 0) warpmin[tid >> 5] = m;
        __syncthreads();
        if (tid < 32) {
            unsigned long long mm = warpmin[tid];
#pragma unroll
            for (int o = 16; o > 0; o >>= 1) {
                unsigned long long other = __shfl_down_sync(0xffffffffu, mm, o);
                mm = (other < mm) ? other : mm;
            }
            if (tid == 0) warpmin[0] = mm;
        }
        __syncthreads();
        unsigned long long best = warpmin[0];
        int e = (int)(best & 0xffffffffull);
        int bi = e >> 7, bj = e & 127;
        if (tid < BATCH) {
            keys[bi * BATCH + tid] = ~0ull;
            keys[tid * BATCH + bj] = ~0ull;
        }
        if (tid == 0) rowm[bi] = bj;
        __syncthreads();
    }

    float part = 0.0f;
    if (tid < BATCH * 3) {
        int i = tid / 3, c = tid % 3;
        float d = lg[rowm[i] * 3 + c] - targets[(i * LSEQ + tref) * 3 + c];
        part = d * d;
    }
    red[tid] = part;
    __syncthreads();
    for (int s = 512; s > 0; s >>= 1) {
        if (tid < s) red[tid] += red[tid + s];
        __syncthreads();
    }
    if (tid == 0) losses[lidx] = red[0] * (1.0f / (BATCH * 3));
}

__global__ void final_mean_kernel(const float* __restrict__ losses, float* __restrict__ out)
{
    if (threadIdx.x == 0 && blockIdx.x == 0) {
        float s = 0.0f;
        for (int i = 0; i < NLIDX; ++i) s += losses[i];
        out[0] = s * (1.0f / NLIDX);
    }
}

// ---------------- launch ----------------
extern "C" void kernel_launch(void* const* d_in, const int* in_sizes, int n_in,
                              void* d_out, int out_size)
{
    (void)in_sizes; (void)n_in; (void)out_size;
    const float* X    = (const float*)d_in[0];
    const float* tg   = (const float*)d_in[1];
    const float* om   = (const float*)d_in[2];
    const float* ph   = (const float*)d_in[3];
    const int*   pm   = (const int*)  d_in[4];
    const float* Wq   = (const float*)d_in[5];
    const float* bq   = (const float*)d_in[6];
    const float* Wk   = (const float*)d_in[7];
    const float* bk   = (const float*)d_in[8];
    const float* Wv   = (const float*)d_in[9];
    const float* bv   = (const float*)d_in[10];
    const float* Wo   = (const float*)d_in[11];
    const float* bo   = (const float*)d_in[12];
    const float* l1g  = (const float*)d_in[13];
    const float* l1b  = (const float*)d_in[14];
    const float* l2g  = (const float*)d_in[15];
    const float* l2b  = (const float*)d_in[16];
    const float* W1   = (const float*)d_in[17];
    const float* b1   = (const float*)d_in[18];
    const float* W2   = (const float*)d_in[19];
    const float* b2   = (const float*)d_in[20];
    const float* lfg  = (const float*)d_in[21];
    const float* lfb  = (const float*)d_in[22];
    const float* Wout = (const float*)d_in[23];
    const float* bout = (const float*)d_in[24];

    float *px, *pqkv, *pbqkv, *plog, *plos;
    __nv_bfloat16 *pah, *pal, *pafh, *pafl, *pwh, *pwl;
    cudaGetSymbolAddress((void**)&px,    g_x);
    cudaGetSymbolAddress((void**)&pqkv,  g_qkv);
    cudaGetSymbolAddress((void**)&pbqkv, g_bqkv);
    cudaGetSymbolAddress((void**)&plog,  g_logits);
    cudaGetSymbolAddress((void**)&plos,  g_losses);
    cudaGetSymbolAddress((void**)&pah,   g_ah);
    cudaGetSymbolAddress((void**)&pal,   g_al);
    cudaGetSymbolAddress((void**)&pafh,  g_afh);
    cudaGetSymbolAddress((void**)&pafl,  g_afl);
    cudaGetSymbolAddress((void**)&pwh,   g_wh);
    cudaGetSymbolAddress((void**)&pwl,   g_wl);

    cudaFuncSetAttribute(match_kernel, cudaFuncAttributeMaxDynamicSharedMemorySize, 131072);
    cudaFuncSetAttribute(gemm_mma<0>, cudaFuncAttributeMaxDynamicSharedMemorySize, DSMEM_BYTES);
    cudaFuncSetAttribute(gemm_mma<1>, cudaFuncAttributeMaxDynamicSharedMemorySize, DSMEM_BYTES);
    cudaFuncSetAttribute(gemm_mma<2>, cudaFuncAttributeMaxDynamicSharedMemorySize, DSMEM_BYTES);

    // -------- prep: 3 batched transpose kernels + fused assemble/biascat --------
    // Launch order puts the first gemm_mma<0> at launch #6 so ncu (-s 5 -c 1)
    // finally captures the GEMM.
    wtrans_sq_kernel<<<dim3(EMB / 32, EMB / 32, NL * 4), 256>>>(Wq, Wk, Wv, Wo, pwh, pwl);
    wtrans_f1_kernel<<<dim3(FF / 32, EMB / 32, NL), 256>>>(W1, pwh, pwl);
    wtrans_f2_kernel<<<dim3(EMB / 32, FF / 32, NL), 256>>>(W2, pwh, pwl);
    assemble_kernel<<<(ASM_TOTAL + 255) / 256, 256>>>(X, tg, om, ph, pm, px, bq, bk, bv, pbqkv);

    dim3 gQKV(NQKV / BN, TOK / BM);   // (18, 180)
    dim3 gE(EMB / BN, TOK / BM);      // (6, 180)
    dim3 gF(FF / BN, TOK / BM);       // (24, 180)
    for (int l = 0; l < NL; ++l) {
        size_t base = (size_t)l * WLAYER;
        ln_split_kernel<<<TOK, 256>>>(px, pah, pal, l1g + l * EMB, l1b + l * EMB);
        gemm_mma<0><<<gQKV, 256, DSMEM_BYTES>>>(pah, pal, pwh + base, pwl + base,
                                                pbqkv + l * NQKV, pqkv, pafh, pafl, NQKV, EMB);
        attn_kernel<<<dim3(NLIDX * BATCH, HEADS), 192>>>(pqkv, pah, pal);
        gemm_mma<1><<<gE, 256, DSMEM_BYTES>>>(pah, pal, pwh + base + (size_t)3 * WQKV,
                                              pwl + base + (size_t)3 * WQKV,
                                              bo + l * EMB, px, pafh, pafl, EMB, EMB);
        ln_split_kernel<<<TOK, 256>>>(px, pah, pal, l2g + l * EMB, l2b + l * EMB);
        gemm_mma<2><<<gF, 256, DSMEM_BYTES>>>(pah, pal, pwh + base + (size_t)4 * WQKV,
                                              pwl + base + (size_t)4 * WQKV,
                                              b1 + l * FF, px, pafh, pafl, FF, EMB);
        gemm_mma<1><<<gE, 256, DSMEM_BYTES>>>(pafh, pafl, pwh + base + (size_t)4 * WQKV + WFFN,
                                              pwl + base + (size_t)4 * WQKV + WFFN,
                                              b2 + l * EMB, px, pafh, pafl, EMB, FF);
    }
    ln_split_kernel<<<TOK, 256>>>(px, pah, pal, lfg, lfb);
    outproj_kernel<<<NLIDX * BATCH, 256>>>(pah, pal, Wout, bout, plog);
    match_kernel<<<NLIDX, 1024, 131072>>>(plog, tg, plos);
    final_mean_kernel<<<1, 32>>>(plos, (float*)d_out);
}

// round 12
// speedup vs baseline: 2.2158x; 1.0157x over previous
#include <cuda_runtime.h>
#include <cuda_bf16.h>
#include <math.h>
#include <stdint.h>

// ---------------- problem constants ----------------
#define BATCH  128
#define LSEQ   16
#define EMB    768
#define DHALF  384
#define HEADS  12
#define HDIM   64
#define NL     6
#define SEQ    12
#define NLIDX  15
#define FF     3072
#define TOK    (NLIDX * BATCH * SEQ)        // 23040
#define TE     (TOK * EMB)                  // 17694720

#define WQKV   (EMB * EMB)                  // 589824
#define WFFN   (EMB * FF)                   // 2359296
#define WLAYER (4 * WQKV + 2 * WFFN)        // 7077888
#define NQKV   (3 * EMB)                    // 2304

// GEMM tiling: 128x128 tile, BK=32, 2-stage cp.async pipeline
#define BM 128
#define BN 128
#define BKT 32
#define STAGE_BYTES 49152      // Ah 12288 + Al 12288 + Bh 12288 + Bl 12288
#define DSMEM_BYTES (2 * STAGE_BYTES)

// ---------------- scratch (device globals; no cudaMalloc allowed) ----------------
__device__ float g_x[TE];                          // fp32 residual stream
__device__ float g_qkv[(size_t)TOK * NQKV];        // fused qkv output (fp32)
__device__ __nv_bfloat16 g_ah[(size_t)TOK * EMB];  // 768-wide GEMM input hi
__device__ __nv_bfloat16 g_al[(size_t)TOK * EMB];  // 768-wide GEMM input lo
__device__ __nv_bfloat16 g_afh[(size_t)TOK * FF];  // 3072-wide GEMM input hi
__device__ __nv_bfloat16 g_afl[(size_t)TOK * FF];  // 3072-wide GEMM input lo
__device__ __nv_bfloat16 g_wh[(size_t)NL * WLAYER];// transposed weights hi  [N][K]
__device__ __nv_bfloat16 g_wl[(size_t)NL * WLAYER];// transposed weights lo
__device__ float g_bqkv[NL * NQKV];
__device__ float g_logits[NLIDX * BATCH * 3];
__device__ float g_losses[NLIDX];

// ---------------- helpers ----------------
static __device__ __forceinline__ unsigned int smem_u32(const void* p) {
    unsigned int a;
    asm("{ .reg .u64 t; cvta.to.shared.u64 t, %1; cvt.u32.u64 %0, t; }"
        : "=r"(a) : "l"(p));
    return a;
}
static __device__ __forceinline__ void cp16(unsigned int dst, const void* src) {
    asm volatile("cp.async.cg.shared.global [%0], [%1], 16;" :: "r"(dst), "l"(src));
}
static __device__ __forceinline__ void cp_commit() {
    asm volatile("cp.async.commit_group;" ::: "memory");
}
static __device__ __forceinline__ void cp_wait1() {
    asm volatile("cp.async.wait_group 1;" ::: "memory");
}
static __device__ __forceinline__ void cp_wait0() {
    asm volatile("cp.async.wait_group 0;" ::: "memory");
}
static __device__ __forceinline__ void ldsm4(unsigned int* r, unsigned int addr) {
    asm volatile("ldmatrix.sync.aligned.m8n8.x4.shared.b16 {%0,%1,%2,%3}, [%4];"
                 : "=r"(r[0]), "=r"(r[1]), "=r"(r[2]), "=r"(r[3]) : "r"(addr));
}
static __device__ __forceinline__ void mma_bf16(float* c, const unsigned int* a,
                                                unsigned int b0, unsigned int b1) {
    asm volatile(
        "mma.sync.aligned.m16n8k16.row.col.f32.bf16.bf16.f32 "
        "{%0,%1,%2,%3}, {%4,%5,%6,%7}, {%8,%9}, {%0,%1,%2,%3};"
        : "+f"(c[0]), "+f"(c[1]), "+f"(c[2]), "+f"(c[3])
        : "r"(a[0]), "r"(a[1]), "r"(a[2]), "r"(a[3]), "r"(b0), "r"(b1));
}
static __device__ __forceinline__ void split_bf16(float v, __nv_bfloat16& h, __nv_bfloat16& l) {
    h = __float2bfloat16_rn(v);
    l = __float2bfloat16_rn(v - __bfloat162float(h));
}
static __device__ __forceinline__ unsigned int pack_bf2(__nv_bfloat16 a, __nv_bfloat16 b) {
    __nv_bfloat162 p; p.x = a; p.y = b;
    return *reinterpret_cast<unsigned int*>(&p);
}

// ---------------- batched weight transpose+split ----------------
__global__ __launch_bounds__(256) void wtrans_sq_kernel(
    const float* __restrict__ Wq, const float* __restrict__ Wk,
    const float* __restrict__ Wv, const float* __restrict__ Wo,
    __nv_bfloat16* __restrict__ hi, __nv_bfloat16* __restrict__ lo)
{
    __shared__ float tile[32][33];
    int z = blockIdx.z;
    int l = z >> 2, m = z & 3;
    const float* W = (m == 0) ? Wq : (m == 1) ? Wk : (m == 2) ? Wv : Wo;
    W += (size_t)l * WQKV;
    size_t obase = (size_t)l * WLAYER + (size_t)m * WQKV;

    int n0 = blockIdx.x * 32, k0 = blockIdx.y * 32;
    int tx = threadIdx.x & 31, ty = threadIdx.x >> 5;
#pragma unroll
    for (int j = 0; j < 4; ++j)
        tile[ty + j * 8][tx] = W[(size_t)(k0 + ty + j * 8) * EMB + n0 + tx];
    __syncthreads();
#pragma unroll
    for (int j = 0; j < 4; ++j) {
        int n = ty + j * 8;
        float v = tile[tx][n];
        __nv_bfloat16 h, l2;
        split_bf16(v, h, l2);
        size_t o = obase + (size_t)(n0 + n) * EMB + k0 + tx;
        hi[o] = h;
        lo[o] = l2;
    }
}

__global__ __launch_bounds__(256) void wtrans_f1_kernel(
    const float* __restrict__ W1, __nv_bfloat16* __restrict__ hi,
    __nv_bfloat16* __restrict__ lo)
{
    __shared__ float tile[32][33];
    int l = blockIdx.z;
    const float* W = W1 + (size_t)l * WFFN;
    size_t obase = (size_t)l * WLAYER + (size_t)4 * WQKV;

    int n0 = blockIdx.x * 32, k0 = blockIdx.y * 32;
    int tx = threadIdx.x & 31, ty = threadIdx.x >> 5;
#pragma unroll
    for (int j = 0; j < 4; ++j)
        tile[ty + j * 8][tx] = W[(size_t)(k0 + ty + j * 8) * FF + n0 + tx];
    __syncthreads();
#pragma unroll
    for (int j = 0; j < 4; ++j) {
        int n = ty + j * 8;
        float v = tile[tx][n];
        __nv_bfloat16 h, l2;
        split_bf16(v, h, l2);
        size_t o = obase + (size_t)(n0 + n) * EMB + k0 + tx;
        hi[o] = h;
        lo[o] = l2;
    }
}

__global__ __launch_bounds__(256) void wtrans_f2_kernel(
    const float* __restrict__ W2, __nv_bfloat16* __restrict__ hi,
    __nv_bfloat16* __restrict__ lo)
{
    __shared__ float tile[32][33];
    int l = blockIdx.z;
    const float* W = W2 + (size_t)l * WFFN;
    size_t obase = (size_t)l * WLAYER + (size_t)4 * WQKV + WFFN;

    int n0 = blockIdx.x * 32, k0 = blockIdx.y * 32;
    int tx = threadIdx.x & 31, ty = threadIdx.x >> 5;
#pragma unroll
    for (int j = 0; j < 4; ++j)
        tile[ty + j * 8][tx] = W[(size_t)(k0 + ty + j * 8) * EMB + n0 + tx];
    __syncthreads();
#pragma unroll
    for (int j = 0; j < 4; ++j) {
        int n = ty + j * 8;
        float v = tile[tx][n];
        __nv_bfloat16 h, l2;
        split_bf16(v, h, l2);
        size_t o = obase + (size_t)(n0 + n) * FF + k0 + tx;
        hi[o] = h;
        lo[o] = l2;
    }
}

// ---------------- input assembly (+ fused qkv bias concat in tail blocks) ----------------
#define ASM_TOTAL (TE + NL * NQKV)
__global__ __launch_bounds__(256) void assemble_kernel(
    const float* __restrict__ X, const float* __restrict__ targets,
    const float* __restrict__ omegas, const float* __restrict__ phases,
    const int* __restrict__ perms, float* __restrict__ xout,
    const float* __restrict__ bq, const float* __restrict__ bk,
    const float* __restrict__ bv, float* __restrict__ bqkv)
{
    int idx = blockIdx.x * blockDim.x + threadIdx.x;
    if (idx >= ASM_TOTAL) return;
    if (idx >= TE) {
        int k = idx - TE;
        int l = k / NQKV, n = k % NQKV;
        float v;
        if (n < EMB) v = bq[l * EMB + n];
        else if (n < 2 * EMB) v = bk[l * EMB + n - EMB];
        else v = bv[l * EMB + n - 2 * EMB];
        bqkv[k] = v;
        return;
    }
    int e = idx % EMB;
    int t = idx / EMB;
    int s = t % SEQ;
    int b = (t / SEQ) % BATCH;
    int lidx = t / (SEQ * BATCH);
    int sb = perms[lidx * BATCH + b];

    float val;
    if (s < 3) {
        int c = s;
        int ti = (e < DHALF) ? (15 - lidx) : (14 - lidx);
        int d  = (e < DHALF) ? e : (e - DHALF);
        float xv = X[(sb * LSEQ + ti) * 3 + c];
        val = cosf(xv * omegas[c * DHALF + d] + phases[c * DHALF + d]);
    } else if (s < 6) {
        int c = s - 3;
        int ti = (16 - lidx) % 16;
        val = targets[(sb * LSEQ + ti) * 3 + c];
    } else {
        val = (float)(15 - lidx);
    }
    xout[idx] = val;
}

// ---------------- layernorm: warp per token, shuffle-only reductions ----------------
__global__ __launch_bounds__(256) void ln_split_kernel(
    const float* __restrict__ in, __nv_bfloat16* __restrict__ oh,
    __nv_bfloat16* __restrict__ ol, const float* __restrict__ gam,
    const float* __restrict__ bet)
{
    int tok  = blockIdx.x * 8 + (threadIdx.x >> 5);
    int lane = threadIdx.x & 31;
    const float* x = in + (size_t)tok * EMB;

    float v[24];
    float s = 0.0f;
#pragma unroll
    for (int j = 0; j < 24; ++j) {
        v[j] = x[lane + j * 32];
        s += v[j];
    }
#pragma unroll
    for (int o = 16; o > 0; o >>= 1) s += __shfl_xor_sync(0xffffffffu, s, o);
    float mu = s * (1.0f / EMB);

    float var = 0.0f;
#pragma unroll
    for (int j = 0; j < 24; ++j) {
        v[j] -= mu;
        var += v[j] * v[j];
    }
#pragma unroll
    for (int o = 16; o > 0; o >>= 1) var += __shfl_xor_sync(0xffffffffu, var, o);
    float rs = rsqrtf(var * (1.0f / EMB) + 1e-3f);

    size_t base = (size_t)tok * EMB;
#pragma unroll
    for (int j = 0; j < 24; ++j) {
        int e = lane + j * 32;
        float r = v[j] * rs * gam[e] + bet[e];
        __nv_bfloat16 h, l;
        split_bf16(r, h, l);
        oh[base + e] = h;
        ol[base + e] = l;
    }
}

// ---------------- bf16x3 mma.sync GEMM body (shared by plain-named wrappers) ----------------
// C[M, Ntot] = A[M, K] @ Wt[Ntot, K]^T, all operands pre-split bf16 hi/lo.
// Tile 128x128, BK=32 (2 k16 chunks), 2 stages, 2 CTAs/SM. 8 warps 2(m) x 4(n).
// mma issue order is term-major within each mi: RAW distance 4 between mmas on
// the same accumulator (was 1).
// EPI 0: Cf = acc + bias ; 1: Cf += acc + bias ; 2: Ch/Cl = split(relu(acc + bias))
template <int EPI>
static __device__ __forceinline__ void gemm_body(
    const __nv_bfloat16* __restrict__ Ah, const __nv_bfloat16* __restrict__ Al,
    const __nv_bfloat16* __restrict__ Bh, const __nv_bfloat16* __restrict__ Bl,
    const float* __restrict__ bias, float* __restrict__ Cf,
    __nv_bfloat16* __restrict__ Ch, __nv_bfloat16* __restrict__ Cl,
    int Ntot, int K)
{
    extern __shared__ __align__(16) char dsm[];
    const int t = threadIdx.x;
    const int lane = t & 31, wid = t >> 5;
    const int wm = wid >> 2, wn = wid & 3;
    const int row0 = blockIdx.y * BM, col0 = blockIdx.x * BN;
    const unsigned int smem = smem_u32(dsm);

    float acc[4][4][4];
#pragma unroll
    for (int i = 0; i < 4; ++i)
#pragma unroll
        for (int j = 0; j < 4; ++j)
#pragma unroll
            for (int k = 0; k < 4; ++k) acc[i][j][k] = 0.0f;

    const int seg   = t & 1;
    const int chunk = (t >> 1) & 1;
    const int rr    = t >> 2;                    // 0..63
    const int koff0 = chunk * 16 + seg * 8;
    const unsigned int dst_base = smem + chunk * 6144 + seg * 16;

    auto load_stage = [&](int kt, int stg) {
        unsigned int sb = dst_base + stg * STAGE_BYTES;
        int koff = kt * BKT + koff0;
#pragma unroll
        for (int i = 0; i < 8; ++i) {
            int ab = i >> 2, hl = (i >> 1) & 1, rh = i & 1;
            int r = rh * 64 + rr;
            const __nv_bfloat16* src;
            if (ab == 0) src = (hl ? Al : Ah) + (size_t)(row0 + r) * K + koff;
            else         src = (hl ? Bl : Bh) + (size_t)(col0 + r) * K + koff;
            cp16(sb + ab * 24576 + hl * 12288 + r * 48, src);
        }
        cp_commit();
    };

    const int arow  = wm * 64 + (lane & 15);
    const int abyte = (lane >> 4) << 4;
    const unsigned int aHb = smem + arow * 48 + abyte;
    const int brow  = wn * 32 + (lane & 7) + ((lane >> 4) << 3);
    const int bbyte = ((lane >> 3) & 1) << 4;
    const unsigned int bHb = smem + 24576 + brow * 48 + bbyte;

    const int nst = K / BKT;
    load_stage(0, 0);
    if (nst > 1) load_stage(1, 1);

    for (int st = 0; st < nst; ++st) {
        if (st + 1 < nst) cp_wait1(); else cp_wait0();
        __syncthreads();
        unsigned int so = (st & 1) * STAGE_BYTES;
#pragma unroll
        for (int ch = 0; ch < 2; ++ch) {
            unsigned int co = so + ch * 6144;
            unsigned int Bfh[2][4], Bfl[2][4];
            ldsm4(Bfh[0], bHb + co);
            ldsm4(Bfh[1], bHb + co + 16 * 48);
            ldsm4(Bfl[0], bHb + co + 12288);
            ldsm4(Bfl[1], bHb + co + 12288 + 16 * 48);
#pragma unroll
            for (int mi = 0; mi < 4; ++mi) {
                unsigned int Afh[4], Afl[4];
                ldsm4(Afh, aHb + co + mi * (16 * 48));
                ldsm4(Afl, aHb + co + 12288 + mi * (16 * 48));
                // term-major: all HH (4 accs), then HL, then LH
#pragma unroll
                for (int p = 0; p < 2; ++p)
#pragma unroll
                    for (int q = 0; q < 2; ++q)
                        mma_bf16(acc[mi][p * 2 + q], Afh, Bfh[p][2 * q], Bfh[p][2 * q + 1]);
#pragma unroll
                for (int p = 0; p < 2; ++p)
#pragma unroll
                    for (int q = 0; q < 2; ++q)
                        mma_bf16(acc[mi][p * 2 + q], Afh, Bfl[p][2 * q], Bfl[p][2 * q + 1]);
#pragma unroll
                for (int p = 0; p < 2; ++p)
#pragma unroll
                    for (int q = 0; q < 2; ++q)
                        mma_bf16(acc[mi][p * 2 + q], Afl, Bfh[p][2 * q], Bfh[p][2 * q + 1]);
            }
        }
        if (st + 2 < nst) {
            __syncthreads();
            load_stage(st + 2, st & 1);
        }
    }

    // ---- epilogue ----
    const int rbase = row0 + wm * 64 + (lane >> 2);
    const int cbase = col0 + wn * 32 + (lane & 3) * 2;
#pragma unroll
    for (int ni = 0; ni < 4; ++ni) {
        int cb = cbase + ni * 8;
        float2 bi = *(const float2*)&bias[cb];
#pragma unroll
        for (int mi = 0; mi < 4; ++mi) {
            float* c = acc[mi][ni];
            size_t o0 = (size_t)(rbase + mi * 16) * Ntot + cb;
            size_t o1 = o0 + (size_t)8 * Ntot;
            if (EPI == 2) {
                float v00 = fmaxf(c[0] + bi.x, 0.0f), v01 = fmaxf(c[1] + bi.y, 0.0f);
                float v10 = fmaxf(c[2] + bi.x, 0.0f), v11 = fmaxf(c[3] + bi.y, 0.0f);
                __nv_bfloat16 h00, l00, h01, l01, h10, l10, h11, l11;
                split_bf16(v00, h00, l00);
                split_bf16(v01, h01, l01);
                split_bf16(v10, h10, l10);
                split_bf16(v11, h11, l11);
                *(unsigned int*)&Ch[o0] = pack_bf2(h00, h01);
                *(unsigned int*)&Cl[o0] = pack_bf2(l00, l01);
                *(unsigned int*)&Ch[o1] = pack_bf2(h10, h11);
                *(unsigned int*)&Cl[o1] = pack_bf2(l10, l11);
            } else {
                float2 v0 = make_float2(c[0] + bi.x, c[1] + bi.y);
                float2 v1 = make_float2(c[2] + bi.x, c[3] + bi.y);
                if (EPI == 1) {
                    float2 p0 = *(float2*)&Cf[o0], p1 = *(float2*)&Cf[o1];
                    v0.x += p0.x; v0.y += p0.y;
                    v1.x += p1.x; v1.y += p1.y;
                }
                *(float2*)&Cf[o0] = v0;
                *(float2*)&Cf[o1] = v1;
            }
        }
    }
}

// plain-named wrappers (ncu text tooling chokes on template names)
__global__ __launch_bounds__(256, 2) void gemm_ep0(
    const __nv_bfloat16* __restrict__ Ah, const __nv_bfloat16* __restrict__ Al,
    const __nv_bfloat16* __restrict__ Bh, const __nv_bfloat16* __restrict__ Bl,
    const float* __restrict__ bias, float* __restrict__ Cf,
    __nv_bfloat16* __restrict__ Ch, __nv_bfloat16* __restrict__ Cl, int Ntot, int K)
{ gemm_body<0>(Ah, Al, Bh, Bl, bias, Cf, Ch, Cl, Ntot, K); }

__global__ __launch_bounds__(256, 2) void gemm_ep1(
    const __nv_bfloat16* __restrict__ Ah, const __nv_bfloat16* __restrict__ Al,
    const __nv_bfloat16* __restrict__ Bh, const __nv_bfloat16* __restrict__ Bl,
    const float* __restrict__ bias, float* __restrict__ Cf,
    __nv_bfloat16* __restrict__ Ch, __nv_bfloat16* __restrict__ Cl, int Ntot, int K)
{ gemm_body<1>(Ah, Al, Bh, Bl, bias, Cf, Ch, Cl, Ntot, K); }

__global__ __launch_bounds__(256, 2) void gemm_ep2(
    const __nv_bfloat16* __restrict__ Ah, const __nv_bfloat16* __restrict__ Al,
    const __nv_bfloat16* __restrict__ Bh, const __nv_bfloat16* __restrict__ Bl,
    const float* __restrict__ bias, float* __restrict__ Cf,
    __nv_bfloat16* __restrict__ Ch, __nv_bfloat16* __restrict__ Cl, int Ntot, int K)
{ gemm_body<2>(Ah, Al, Bh, Bl, bias, Cf, Ch, Cl, Ntot, K); }

// ---------------- attention: reads fused qkv (stride 2304), writes hi/lo o ----------------
__global__ __launch_bounds__(192) void attn_kernel(
    const float* __restrict__ qkv, __nv_bfloat16* __restrict__ oh,
    __nv_bfloat16* __restrict__ ol)
{
    int inst = blockIdx.x;
    int h    = blockIdx.y;
    int base = inst * SEQ;
    int tid  = threadIdx.x;

    __shared__ float qs[SEQ][HDIM], ks[SEQ][HDIM], vs[SEQ][HDIM];
    __shared__ float sc[SEQ][SEQ], ps[SEQ][SEQ];

    for (int idx = tid; idx < SEQ * HDIM; idx += 192) {
        int s = idx >> 6, d = idx & 63;
        size_t g = (size_t)(base + s) * NQKV + h * HDIM + d;
        qs[s][d] = qkv[g];
        ks[s][d] = qkv[g + EMB];
        vs[s][d] = qkv[g + 2 * EMB];
    }
    __syncthreads();

    if (tid < SEQ * SEQ) {
        int i = tid / SEQ, j = tid % SEQ;
        float a = 0.0f;
#pragma unroll
        for (int d = 0; d < HDIM; ++d) a += qs[i][d] * ks[j][d];
        sc[i][j] = a * 0.125f;
    }
    __syncthreads();

    if (tid < SEQ) {
        float mx = -1e30f;
#pragma unroll
        for (int j = 0; j < SEQ; ++j) mx = fmaxf(mx, sc[tid][j]);
        float sum = 0.0f;
#pragma unroll
        for (int j = 0; j < SEQ; ++j) { float ev = expf(sc[tid][j] - mx); ps[tid][j] = ev; sum += ev; }
        float inv = 1.0f / sum;
#pragma unroll
        for (int j = 0; j < SEQ; ++j) ps[tid][j] *= inv;
    }
    __syncthreads();

    for (int idx = tid; idx < SEQ * HDIM; idx += 192) {
        int i = idx >> 6, d = idx & 63;
        float a = 0.0f;
#pragma unroll
        for (int j = 0; j < SEQ; ++j) a += ps[i][j] * vs[j][d];
        __nv_bfloat16 hh, ll;
        split_bf16(a, hh, ll);
        size_t g = (size_t)(base + i) * EMB + h * HDIM + d;
        oh[g] = hh;
        ol[g] = ll;
    }
}

// ---------------- output projection (reads hi+lo reconstructed) ----------------
__global__ __launch_bounds__(256) void outproj_kernel(
    const __nv_bfloat16* __restrict__ hh, const __nv_bfloat16* __restrict__ hl,
    const float* __restrict__ Wout, const float* __restrict__ bout,
    float* __restrict__ logits)
{
    __shared__ float r0[256], r1[256], r2[256];
    int inst = blockIdx.x;
    int tid = threadIdx.x;
    size_t base = (size_t)inst * (SEQ * EMB);
    float a0 = 0, a1 = 0, a2 = 0;
    for (int kk = tid; kk < SEQ * EMB; kk += 256) {
        float x = __bfloat162float(hh[base + kk]) + __bfloat162float(hl[base + kk]);
        const float* w = Wout + kk * 3;
        a0 += x * w[0]; a1 += x * w[1]; a2 += x * w[2];
    }
    r0[tid] = a0; r1[tid] = a1; r2[tid] = a2;
    __syncthreads();
    for (int s = 128; s > 0; s >>= 1) {
        if (tid < s) { r0[tid] += r0[tid + s]; r1[tid] += r1[tid + s]; r2[tid] += r2[tid + s]; }
        __syncthreads();
    }
    if (tid == 0) {
        logits[inst * 3 + 0] = r0[0] + bout[0];
        logits[inst * 3 + 1] = r1[0] + bout[1];
        logits[inst * 3 + 2] = r2[0] + bout[2];
    }
}

// ---------------- greedy matching + loss ----------------
__global__ __launch_bounds__(1024) void match_kernel(
    const float* __restrict__ logits, const float* __restrict__ targets,
    float* __restrict__ losses)
{
    extern __shared__ unsigned long long keys[];
    __shared__ int rowm[BATCH];
    __shared__ unsigned long long warpmin[32];
    __shared__ float red[1024];

    int lidx = blockIdx.x;
    int tid = threadIdx.x;
    int tref = 15 - lidx;
    const float* lg = logits + lidx * BATCH * 3;

    for (int e = tid; e < BATCH * BATCH; e += 1024) {
        int i = e >> 7, j = e & 127;
        float dx = lg[i * 3 + 0] - targets[(j * LSEQ + tref) * 3 + 0];
        float dy = lg[i * 3 + 1] - targets[(j * LSEQ + tref) * 3 + 1];
        float dz = lg[i * 3 + 2] - targets[(j * LSEQ + tref) * 3 + 2];
        float c = sqrtf(dx * dx + dy * dy + dz * dz + 1e-12f);
        keys[e] = ((unsigned long long)__float_as_uint(c) << 32) | (unsigned int)e;
    }
    __syncthreads();

    for (int r = 0; r < BATCH; ++r) {
        unsigned long long m = ~0ull;
        for (int e = tid; e < BATCH * BATCH; e += 1024) {
            unsigned long long kk = keys[e];
            m = (kk < m) ? kk : m;
        }
#pragma unroll
        for (int o = 16; o > 0; o >>= 1) {
            unsigned long long other = __shfl_down_sync(0xffffffffu, m, o);
            m = (other < m) ? other : m;
        }
        if ((tid & 31) == 0) warpmin[tid >> 5] = m;
        __syncthreads();
        if (tid < 32) {
            unsigned long long mm = warpmin[tid];
#pragma unroll
            for (int o = 16; o > 0; o >>= 1) {
                unsigned long long other = __shfl_down_sync(0xffffffffu, mm, o);
                mm = (other < mm) ? other : mm;
            }
            if (tid == 0) warpmin[0] = mm;
        }
        __syncthreads();
        unsigned long long best = warpmin[0];
        int e = (int)(best & 0xffffffffull);
        int bi = e >> 7, bj = e & 127;
        if (tid < BATCH) {
            keys[bi * BATCH + tid] = ~0ull;
            keys[tid * BATCH + bj] = ~0ull;
        }
        if (tid == 0) rowm[bi] = bj;
        __syncthreads();
    }

    float part = 0.0f;
    if (tid < BATCH * 3) {
        int i = tid / 3, c = tid % 3;
        float d = lg[rowm[i] * 3 + c] - targets[(i * LSEQ + tref) * 3 + c];
        part = d * d;
    }
    red[tid] = part;
    __syncthreads();
    for (int s = 512; s > 0; s >>= 1) {
        if (tid < s) red[tid] += red[tid + s];
        __syncthreads();
    }
    if (tid == 0) losses[lidx] = red[0] * (1.0f / (BATCH * 3));
}

__global__ void final_mean_kernel(const float* __restrict__ losses, float* __restrict__ out)
{
    if (threadIdx.x == 0 && blockIdx.x == 0) {
        float s = 0.0f;
        for (int i = 0; i < NLIDX; ++i) s += losses[i];
        out[0] = s * (1.0f / NLIDX);
    }
}

// ---------------- launch ----------------
extern "C" void kernel_launch(void* const* d_in, const int* in_sizes, int n_in,
                              void* d_out, int out_size)
{
    (void)in_sizes; (void)n_in; (void)out_size;
    const float* X    = (const float*)d_in[0];
    const float* tg   = (const float*)d_in[1];
    const float* om   = (const float*)d_in[2];
    const float* ph   = (const float*)d_in[3];
    const int*   pm   = (const int*)  d_in[4];
    const float* Wq   = (const float*)d_in[5];
    const float* bq   = (const float*)d_in[6];
    const float* Wk   = (const float*)d_in[7];
    const float* bk   = (const float*)d_in[8];
    const float* Wv   = (const float*)d_in[9];
    const float* bv   = (const float*)d_in[10];
    const float* Wo   = (const float*)d_in[11];
    const float* bo   = (const float*)d_in[12];
    const float* l1g  = (const float*)d_in[13];
    const float* l1b  = (const float*)d_in[14];
    const float* l2g  = (const float*)d_in[15];
    const float* l2b  = (const float*)d_in[16];
    const float* W1   = (const float*)d_in[17];
    const float* b1   = (const float*)d_in[18];
    const float* W2   = (const float*)d_in[19];
    const float* b2   = (const float*)d_in[20];
    const float* lfg  = (const float*)d_in[21];
    const float* lfb  = (const float*)d_in[22];
    const float* Wout = (const float*)d_in[23];
    const float* bout = (const float*)d_in[24];

    float *px, *pqkv, *pbqkv, *plog, *plos;
    __nv_bfloat16 *pah, *pal, *pafh, *pafl, *pwh, *pwl;
    cudaGetSymbolAddress((void**)&px,    g_x);
    cudaGetSymbolAddress((void**)&pqkv,  g_qkv);
    cudaGetSymbolAddress((void**)&pbqkv, g_bqkv);
    cudaGetSymbolAddress((void**)&plog,  g_logits);
    cudaGetSymbolAddress((void**)&plos,  g_losses);
    cudaGetSymbolAddress((void**)&pah,   g_ah);
    cudaGetSymbolAddress((void**)&pal,   g_al);
    cudaGetSymbolAddress((void**)&pafh,  g_afh);
    cudaGetSymbolAddress((void**)&pafl,  g_afl);
    cudaGetSymbolAddress((void**)&pwh,   g_wh);
    cudaGetSymbolAddress((void**)&pwl,   g_wl);

    cudaFuncSetAttribute(match_kernel, cudaFuncAttributeMaxDynamicSharedMemorySize, 131072);
    cudaFuncSetAttribute(gemm_ep0, cudaFuncAttributeMaxDynamicSharedMemorySize, DSMEM_BYTES);
    cudaFuncSetAttribute(gemm_ep1, cudaFuncAttributeMaxDynamicSharedMemorySize, DSMEM_BYTES);
    cudaFuncSetAttribute(gemm_ep2, cudaFuncAttributeMaxDynamicSharedMemorySize, DSMEM_BYTES);

    // prep: first GEMM lands at launch #6 for the ncu -s 5 -c 1 window
    wtrans_sq_kernel<<<dim3(EMB / 32, EMB / 32, NL * 4), 256>>>(Wq, Wk, Wv, Wo, pwh, pwl);
    wtrans_f1_kernel<<<dim3(FF / 32, EMB / 32, NL), 256>>>(W1, pwh, pwl);
    wtrans_f2_kernel<<<dim3(EMB / 32, FF / 32, NL), 256>>>(W2, pwh, pwl);
    assemble_kernel<<<(ASM_TOTAL + 255) / 256, 256>>>(X, tg, om, ph, pm, px, bq, bk, bv, pbqkv);

    dim3 gQKV(NQKV / BN, TOK / BM);   // (18, 180)
    dim3 gE(EMB / BN, TOK / BM);      // (6, 180)
    dim3 gF(FF / BN, TOK / BM);       // (24, 180)
    for (int l = 0; l < NL; ++l) {
        size_t base = (size_t)l * WLAYER;
        ln_split_kernel<<<TOK / 8, 256>>>(px, pah, pal, l1g + l * EMB, l1b + l * EMB);
        gemm_ep0<<<gQKV, 256, DSMEM_BYTES>>>(pah, pal, pwh + base, pwl + base,
                                             pbqkv + l * NQKV, pqkv, pafh, pafl, NQKV, EMB);
        attn_kernel<<<dim3(NLIDX * BATCH, HEADS), 192>>>(pqkv, pah, pal);
        gemm_ep1<<<gE, 256, DSMEM_BYTES>>>(pah, pal, pwh + base + (size_t)3 * WQKV,
                                           pwl + base + (size_t)3 * WQKV,
                                           bo + l * EMB, px, pafh, pafl, EMB, EMB);
        ln_split_kernel<<<TOK / 8, 256>>>(px, pah, pal, l2g + l * EMB, l2b + l * EMB);
        gemm_ep2<<<gF, 256, DSMEM_BYTES>>>(pah, pal, pwh + base + (size_t)4 * WQKV,
                                           pwl + base + (size_t)4 * WQKV,
                                           b1 + l * FF, px, pafh, pafl, FF, EMB);
        gemm_ep1<<<gE, 256, DSMEM_BYTES>>>(pafh, pafl, pwh + base + (size_t)4 * WQKV + WFFN,
                                           pwl + base + (size_t)4 * WQKV + WFFN,
                                           b2 + l * EMB, px, pafh, pafl, EMB, FF);
    }
    ln_split_kernel<<<TOK / 8, 256>>>(px, pah, pal, lfg, lfb);
    outproj_kernel<<<NLIDX * BATCH, 256>>>(pah, pal, Wout, bout, plog);
    match_kernel<<<NLIDX, 1024, 131072>>>(plog, tg, plos);
    final_mean_kernel<<<1, 32>>>(plos, (float*)d_out);
}